// round 5
// baseline (speedup 1.0000x reference)
#include <cuda_runtime.h>
#include <math_constants.h>
#include <cstdint>

#define B_  4
#define C_  512
#define HC_ 256
#define N_  4096

// ---------------------------------------------------------------------------
// Device scratch.  "Pairs" buffers store (hi, lo) 3xTF32 splits interleaved.
// ---------------------------------------------------------------------------
__device__ float2 g_xts[(size_t)B_ * N_ * C_];    // x^T split: [b][n][c]
__device__ float2 g_Ws [(size_t)(HC_ + HC_ + C_) * C_]; // Wf|Wg|Wh split
__device__ float2 g_fts[(size_t)B_ * N_ * HC_];   // f^T split: [b][n][hc]
__device__ float2 g_gts[(size_t)B_ * N_ * HC_];   // g^T split: [b][n][hc]
__device__ float2 g_hs [(size_t)B_ * C_ * N_];    // h split:   [b][c][n]
__device__ float  g_E  [(size_t)B_ * N_ * N_];    // energy [b][j][k]
__device__ float2 g_corr2[(size_t)B_ * N_ * N_];  // softmax(corr) split [b][j][k]
__device__ float  g_part[(size_t)B_ * 32 * N_];   // colmean partials

// ---------------------------------------------------------------------------
// Helpers (baseline PTX only — ptxas targets sm_103, no 'a'-gated instrs)
// ---------------------------------------------------------------------------
__device__ __forceinline__ uint32_t su32(const void* p) {
    uint32_t a;
    asm("{ .reg .u64 t; cvta.to.shared.u64 t, %1; cvt.u32.u64 %0, t; }" : "=r"(a) : "l"(p));
    return a;
}
__device__ __forceinline__ void cp_async16(uint32_t dst, const void* src) {
    asm volatile("cp.async.cg.shared.global [%0], [%1], 16;" :: "r"(dst), "l"(src) : "memory");
}
__device__ __forceinline__ void cp_commit() {
    asm volatile("cp.async.commit_group;" ::: "memory");
}
__device__ __forceinline__ void cp_wait0() {
    asm volatile("cp.async.wait_group 0;" ::: "memory");
}
__device__ __forceinline__ void cp_wait1() {
    asm volatile("cp.async.wait_group 1;" ::: "memory");
}
__device__ __forceinline__ uint32_t f2tf(float f) {
    uint32_t r;
    asm("cvt.rna.tf32.f32 %0, %1;" : "=r"(r) : "f"(f));
    return r;
}
__device__ __forceinline__ float2 split_tf(float v) {
    uint32_t hi = f2tf(v);
    uint32_t lo = f2tf(v - __uint_as_float(hi));
    return make_float2(__uint_as_float(hi), __uint_as_float(lo));
}
__device__ __forceinline__ void mma_tf32(float* d, const uint32_t* a, const uint32_t* b) {
    asm volatile(
        "mma.sync.aligned.m16n8k8.row.col.f32.tf32.tf32.f32 "
        "{%0,%1,%2,%3}, {%4,%5,%6,%7}, {%8,%9}, {%0,%1,%2,%3};"
        : "+f"(d[0]), "+f"(d[1]), "+f"(d[2]), "+f"(d[3])
        : "r"(a[0]), "r"(a[1]), "r"(a[2]), "r"(a[3]), "r"(b[0]), "r"(b[1]));
}

extern __shared__ char dynsm_c[];

// ---------------------------------------------------------------------------
// GEMM core: D[128 x 128] += A[128 x K] @ B[128 x K]^T  (3xTF32 HMMA)
// A, B are PRE-SPLIT (hi,lo) float2, K-contig, row strides lda/ldb in pairs.
// smem: 3 stages x (A 16KB + B 16KB) = 96KB.  k-tile = 16 pairs (128B/row).
// 8 warps: wr = warp>>2 (2 M-groups of 64), wc = warp&3 (4 N-groups of 32).
// Tile row = 128B: 8 chunks of 16B, chunk slot swizzled by c ^ (r&7).
// ---------------------------------------------------------------------------
__device__ __forceinline__ void gemm_core(
    const float2* __restrict__ A, int lda,
    const float2* __restrict__ Bm, int ldb,
    int nKt, float acc[4][4][4])
{
    char* sm = dynsm_c;
    const int tid  = threadIdx.x;
    const int c8   = tid & 7;          // 16B chunk within row
    const int r0   = tid >> 3;         // 0..31
    const int lane = tid & 31, warp = tid >> 5;
    const int wr = warp >> 2, wc = warp & 3;
    const int g = lane >> 2, tg = lane & 3;
    const int par8 = (tg & 1) * 8;     // byte offset for odd k within chunk

    auto issue = [&](int stage, int kt) {
        const int k0 = kt * 16;        // pair offset
        char* sa = sm + stage * 32768;
        char* sb = sa + 16384;
        const int slot = (c8 ^ (r0 & 7)) * 16;
        #pragma unroll
        for (int p = 0; p < 4; ++p) {
            const int r = p * 32 + r0;
            cp_async16(su32(sa + r * 128 + slot), A  + (size_t)r * lda + k0 + c8 * 2);
            cp_async16(su32(sb + r * 128 + slot), Bm + (size_t)r * ldb + k0 + c8 * 2);
        }
        cp_commit();
    };

    issue(0, 0);
    issue(1, 1);

    for (int kt = 0; kt < nKt; ++kt) {
        const int s = kt % 3;
        if (kt + 1 < nKt) cp_wait1(); else cp_wait0();
        __syncthreads();
        if (kt + 2 < nKt) issue((kt + 2) % 3, kt + 2);

        const char* sa = sm + s * 32768;
        const char* sb = sa + 16384;

        #pragma unroll
        for (int k8 = 0; k8 < 2; ++k8) {
            // chunk slots for k = kq (= k8*8 + tg) and kq+4
            const int s0 = ((((k8 << 2) | (tg >> 1))    ) ^ g) * 16 + par8;
            const int s1 = ((((k8 << 2) | (tg >> 1)) + 2) ^ g) * 16 + par8;

            uint32_t ahi[4][4], alo[4][4], bhi[4][2], blo[4][2];
            #pragma unroll
            for (int am = 0; am < 4; ++am) {
                const char* row0 = sa + (size_t)(wr * 64 + am * 16 + g) * 128;
                const char* row1 = row0 + 8 * 128;
                float2 p00 = *reinterpret_cast<const float2*>(row0 + s0);
                float2 p10 = *reinterpret_cast<const float2*>(row1 + s0);
                float2 p01 = *reinterpret_cast<const float2*>(row0 + s1);
                float2 p11 = *reinterpret_cast<const float2*>(row1 + s1);
                ahi[am][0] = __float_as_uint(p00.x); alo[am][0] = __float_as_uint(p00.y);
                ahi[am][1] = __float_as_uint(p10.x); alo[am][1] = __float_as_uint(p10.y);
                ahi[am][2] = __float_as_uint(p01.x); alo[am][2] = __float_as_uint(p01.y);
                ahi[am][3] = __float_as_uint(p11.x); alo[am][3] = __float_as_uint(p11.y);
            }
            #pragma unroll
            for (int bn = 0; bn < 4; ++bn) {
                const char* row = sb + (size_t)(wc * 32 + bn * 8 + g) * 128;
                float2 q0 = *reinterpret_cast<const float2*>(row + s0);
                float2 q1 = *reinterpret_cast<const float2*>(row + s1);
                bhi[bn][0] = __float_as_uint(q0.x); blo[bn][0] = __float_as_uint(q0.y);
                bhi[bn][1] = __float_as_uint(q1.x); blo[bn][1] = __float_as_uint(q1.y);
            }
            // pass 1: hi*hi
            #pragma unroll
            for (int am = 0; am < 4; ++am)
                #pragma unroll
                for (int bn = 0; bn < 4; ++bn)
                    mma_tf32(acc[am][bn], ahi[am], bhi[bn]);
            // pass 2: hi*lo
            #pragma unroll
            for (int am = 0; am < 4; ++am)
                #pragma unroll
                for (int bn = 0; bn < 4; ++bn)
                    mma_tf32(acc[am][bn], ahi[am], blo[bn]);
            // pass 3: lo*hi
            #pragma unroll
            for (int am = 0; am < 4; ++am)
                #pragma unroll
                for (int bn = 0; bn < 4; ++bn)
                    mma_tf32(acc[am][bn], alo[am], bhi[bn]);
        }
    }
}

// Epilogue: plain fp32 store. Out pre-offset to tile; ld in floats.
__device__ __forceinline__ void epi_store_f32(
    float acc[4][4][4], float* __restrict__ Out, int ld,
    const float* __restrict__ bias_row)
{
    const int lane = threadIdx.x & 31, warp = threadIdx.x >> 5;
    const int wr = warp >> 2, wc = warp & 3;
    const int g = lane >> 2, tg = lane & 3;
    #pragma unroll
    for (int am = 0; am < 4; ++am) {
        const int r = wr * 64 + am * 16 + g;
        const float br0 = bias_row ? bias_row[r]     : 0.f;
        const float br1 = bias_row ? bias_row[r + 8] : 0.f;
        #pragma unroll
        for (int bn = 0; bn < 4; ++bn) {
            const int c = wc * 32 + bn * 8 + tg * 2;
            float2 v0 = { acc[am][bn][0] + br0, acc[am][bn][1] + br0 };
            float2 v1 = { acc[am][bn][2] + br1, acc[am][bn][3] + br1 };
            *reinterpret_cast<float2*>(&Out[(size_t)r       * ld + c]) = v0;
            *reinterpret_cast<float2*>(&Out[(size_t)(r + 8) * ld + c]) = v1;
        }
    }
}

// Epilogue: split (hi,lo) store into a pairs buffer. ld in pairs.
__device__ __forceinline__ void epi_store_pairs(
    float acc[4][4][4], float2* __restrict__ Out, int ld,
    const float* __restrict__ bias_col, const float* __restrict__ bias_row)
{
    const int lane = threadIdx.x & 31, warp = threadIdx.x >> 5;
    const int wr = warp >> 2, wc = warp & 3;
    const int g = lane >> 2, tg = lane & 3;
    #pragma unroll
    for (int am = 0; am < 4; ++am) {
        const int r = wr * 64 + am * 16 + g;
        const float br0 = bias_row ? bias_row[r]     : 0.f;
        const float br1 = bias_row ? bias_row[r + 8] : 0.f;
        #pragma unroll
        for (int bn = 0; bn < 4; ++bn) {
            const int c = wc * 32 + bn * 8 + tg * 2;
            const float b0 = bias_col ? bias_col[c]     : 0.f;
            const float b1 = bias_col ? bias_col[c + 1] : 0.f;
            float2 e00 = split_tf(acc[am][bn][0] + b0 + br0);
            float2 e01 = split_tf(acc[am][bn][1] + b1 + br0);
            float2 e10 = split_tf(acc[am][bn][2] + b0 + br1);
            float2 e11 = split_tf(acc[am][bn][3] + b1 + br1);
            float4 v0 = { e00.x, e00.y, e01.x, e01.y };
            float4 v1 = { e10.x, e10.y, e11.x, e11.y };
            *reinterpret_cast<float4*>(&Out[(size_t)r       * ld + c]) = v0;
            *reinterpret_cast<float4*>(&Out[(size_t)(r + 8) * ld + c]) = v1;
        }
    }
}

// ---------------------------------------------------------------------------
// Producers
// ---------------------------------------------------------------------------
__global__ __launch_bounds__(256) void split_w_kernel(
    const float* __restrict__ Wf, const float* __restrict__ Wg,
    const float* __restrict__ Wh)
{
    const int i = blockIdx.x * 256 + threadIdx.x;
    const int NW = (HC_ + HC_ + C_) * C_;
    if (i >= NW) return;
    float v;
    if (i < HC_ * C_)           v = Wf[i];
    else if (i < 2 * HC_ * C_)  v = Wg[i - HC_ * C_];
    else                        v = Wh[i - 2 * HC_ * C_];
    g_Ws[i] = split_tf(v);
}

__global__ __launch_bounds__(256) void transpose_x_kernel(const float* __restrict__ x)
{
    __shared__ float t[32][33];
    const int b = blockIdx.z, n0 = blockIdx.x * 32, c0 = blockIdx.y * 32;
    const int tx = threadIdx.x, ty = threadIdx.y;
    const float* X = x + (size_t)b * C_ * N_;
    float2* XT = g_xts + (size_t)b * N_ * C_;
    #pragma unroll
    for (int i = 0; i < 4; ++i)
        t[ty + i * 8][tx] = X[(size_t)(c0 + ty + i * 8) * N_ + n0 + tx];
    __syncthreads();
    #pragma unroll
    for (int i = 0; i < 4; ++i)
        XT[(size_t)(n0 + ty + i * 8) * C_ + c0 + tx] = split_tf(t[tx][ty + i * 8]);
}

// ---------------------------------------------------------------------------
// GEMM kernels
// ---------------------------------------------------------------------------
// f^T/g^T: D[n][o] = xt[n][:] . W[o][:]  -> split pairs, row-major [n][o]
__global__ __launch_bounds__(256) void projfg_kernel(
    const float* __restrict__ bf, const float* __restrict__ bg)
{
    const int b = blockIdx.z, n0 = blockIdx.x * 128, ot = blockIdx.y;
    const float2* A = g_xts + ((size_t)b * N_ + n0) * C_;
    const float2* W; const float* bias; float2* Out; int o0;
    if (ot < 2) { W = g_Ws + (size_t)(ot * 128) * C_;            bias = bf + ot * 128;       Out = g_fts + (size_t)b * N_ * HC_; o0 = ot * 128; }
    else        { W = g_Ws + (size_t)(HC_ + (ot - 2) * 128) * C_; bias = bg + (ot - 2) * 128; Out = g_gts + (size_t)b * N_ * HC_; o0 = (ot - 2) * 128; }

    float acc[4][4][4] = {};
    gemm_core(A, C_, W, C_, C_ / 16, acc);
    epi_store_pairs(acc, Out + (size_t)n0 * HC_ + o0, HC_, bias, nullptr);
}

// h: D[c][n] = Wh[c][:] . xt[n][:]  -> split pairs, row-major [c][n]
__global__ __launch_bounds__(256) void projh_kernel(const float* __restrict__ bh)
{
    const int b = blockIdx.z, n0 = blockIdx.x * 128, c0 = blockIdx.y * 128;
    const float2* A  = g_Ws + (size_t)(2 * HC_ + c0) * C_;
    const float2* Bm = g_xts + ((size_t)b * N_ + n0) * C_;

    float acc[4][4][4] = {};
    gemm_core(A, C_, Bm, C_, C_ / 16, acc);
    epi_store_pairs(acc, g_hs + (size_t)b * C_ * N_ + (size_t)c0 * N_ + n0, N_, nullptr, bh + c0);
}

// energy: D[j][k] = ft[j][:] . gt[k][:]  -> plain fp32 E
__global__ __launch_bounds__(256) void energy_kernel()
{
    const int b = blockIdx.z, k0 = blockIdx.x * 128, j0 = blockIdx.y * 128;
    const float2* A  = g_fts + ((size_t)b * N_ + j0) * HC_;
    const float2* Bm = g_gts + ((size_t)b * N_ + k0) * HC_;

    float acc[4][4][4] = {};
    gemm_core(A, HC_, Bm, HC_, HC_ / 16, acc);
    epi_store_f32(acc, g_E + (size_t)b * N_ * N_ + (size_t)j0 * N_ + k0, N_, nullptr);
}

// residual: D[c][j] = h[c][:] . corr[j][:]  -> plain fp32 to harness out
__global__ __launch_bounds__(256) void residual_kernel(float* __restrict__ out)
{
    const int b = blockIdx.z, j0 = blockIdx.x * 128, c0 = blockIdx.y * 128;
    const float2* A  = g_hs + (size_t)b * C_ * N_ + (size_t)c0 * N_;
    const float2* Bm = g_corr2 + (size_t)b * N_ * N_ + (size_t)j0 * N_;

    float acc[4][4][4] = {};
    gemm_core(A, N_, Bm, N_, N_ / 16, acc);
    epi_store_f32(acc, out + (size_t)b * C_ * N_ + (size_t)c0 * N_ + j0, N_, nullptr);
}

// ---------------------------------------------------------------------------
// Softmax: read float E row, write split corr pairs
// ---------------------------------------------------------------------------
__global__ __launch_bounds__(256) void softmax_kernel()
{
    const int b = blockIdx.y;
    const int j = blockIdx.x;
    const float* row = g_E + ((size_t)b * N_ + j) * N_;
    float2* rout = g_corr2 + ((size_t)b * N_ + j) * N_;
    const int tid = threadIdx.x;

    float v[16];
    float m = -CUDART_INF_F;
    #pragma unroll
    for (int i = 0; i < 16; ++i) { v[i] = row[tid + i * 256]; m = fmaxf(m, v[i]); }

    __shared__ float red[8];
    #pragma unroll
    for (int o = 16; o; o >>= 1) m = fmaxf(m, __shfl_xor_sync(0xffffffffu, m, o));
    if ((tid & 31) == 0) red[tid >> 5] = m;
    __syncthreads();
    {
        float t = (tid < 8) ? red[tid] : -CUDART_INF_F;
        #pragma unroll
        for (int o = 4; o; o >>= 1) t = fmaxf(t, __shfl_xor_sync(0xffffffffu, t, o));
        if (tid == 0) red[0] = t;
    }
    __syncthreads();
    m = red[0];
    __syncthreads();

    float s = 0.f;
    #pragma unroll
    for (int i = 0; i < 16; ++i) { v[i] = __expf(v[i] - m); s += v[i]; }
    #pragma unroll
    for (int o = 16; o; o >>= 1) s += __shfl_xor_sync(0xffffffffu, s, o);
    if ((tid & 31) == 0) red[tid >> 5] = s;
    __syncthreads();
    {
        float t = (tid < 8) ? red[tid] : 0.f;
        #pragma unroll
        for (int o = 4; o; o >>= 1) t += __shfl_xor_sync(0xffffffffu, t, o);
        if (tid == 0) red[0] = t;
    }
    __syncthreads();
    const float inv = 1.0f / red[0];

    #pragma unroll
    for (int i = 0; i < 16; ++i) rout[tid + i * 256] = split_tf(v[i] * inv);
}

// ---------------------------------------------------------------------------
// Column mean of corr (reads split pairs, hi+lo)
// ---------------------------------------------------------------------------
__global__ __launch_bounds__(256) void colmean_part_kernel()
{
    const int b = blockIdx.z, jb = blockIdx.y;
    const int col = blockIdx.x * 256 + threadIdx.x;
    const float2* E = g_corr2 + (size_t)b * N_ * N_ + (size_t)jb * 128 * N_;
    float s = 0.f;
    #pragma unroll 8
    for (int j = 0; j < 128; ++j) {
        float2 p = E[(size_t)j * N_ + col];
        s += p.x + p.y;
    }
    g_part[((size_t)b * 32 + jb) * N_ + col] = s;
}

__global__ __launch_bounds__(256) void colmean_final_kernel(float* __restrict__ out)
{
    const int b = blockIdx.y;
    const int col = blockIdx.x * 256 + threadIdx.x;
    float s = 0.f;
    #pragma unroll
    for (int p = 0; p < 32; ++p) s += g_part[((size_t)b * 32 + p) * N_ + col];
    out[(size_t)B_ * C_ * N_ + (size_t)b * N_ + col] = s * (1.0f / N_);
}

// ---------------------------------------------------------------------------
extern "C" void kernel_launch(void* const* d_in, const int* in_sizes, int n_in,
                              void* d_out, int out_size)
{
    const float* x  = (const float*)d_in[0];
    const float* Wf = (const float*)d_in[1];
    const float* bf = (const float*)d_in[2];
    const float* Wg = (const float*)d_in[3];
    const float* bg = (const float*)d_in[4];
    const float* Wh = (const float*)d_in[5];
    const float* bh = (const float*)d_in[6];
    float* out = (float*)d_out;

    const int SMEM = 98304;  // 3 stages x (16KB A + 16KB B)
    cudaFuncSetAttribute(projfg_kernel,   cudaFuncAttributeMaxDynamicSharedMemorySize, SMEM);
    cudaFuncSetAttribute(projh_kernel,    cudaFuncAttributeMaxDynamicSharedMemorySize, SMEM);
    cudaFuncSetAttribute(energy_kernel,   cudaFuncAttributeMaxDynamicSharedMemorySize, SMEM);
    cudaFuncSetAttribute(residual_kernel, cudaFuncAttributeMaxDynamicSharedMemorySize, SMEM);

    const int NW = (HC_ + HC_ + C_) * C_;
    split_w_kernel<<<(NW + 255) / 256, 256>>>(Wf, Wg, Wh);
    transpose_x_kernel<<<dim3(N_ / 32, C_ / 32, B_), dim3(32, 8)>>>(x);
    projfg_kernel<<<dim3(32, 4, B_), 256, SMEM>>>(bf, bg);
    projh_kernel<<<dim3(32, 4, B_), 256, SMEM>>>(bh);
    energy_kernel<<<dim3(32, 32, B_), 256, SMEM>>>();
    softmax_kernel<<<dim3(N_, B_), 256>>>();
    colmean_part_kernel<<<dim3(16, 32, B_), 256>>>();
    colmean_final_kernel<<<dim3(16, B_), 256>>>(out);
    residual_kernel<<<dim3(32, 4, B_), 256, SMEM>>>(out);
}

// round 6
// speedup vs baseline: 1.2498x; 1.2498x over previous
#include <cuda_runtime.h>
#include <math_constants.h>
#include <cstdint>

#define B_  4
#define C_  512
#define HC_ 256
#define N_  4096

// ---------------------------------------------------------------------------
// Device scratch
// ---------------------------------------------------------------------------
__device__ float g_xt[(size_t)B_ * N_ * C_];    // x^T: [b][n][c]
__device__ float g_ft[(size_t)B_ * N_ * HC_];   // f^T: [b][n][hc]
__device__ float g_gt[(size_t)B_ * N_ * HC_];   // g^T: [b][n][hc]
__device__ float g_h [(size_t)B_ * C_ * N_];    // h:   [b][c][n]
__device__ float g_E [(size_t)B_ * N_ * N_];    // energy / correlation [b][j][k]
__device__ float g_part[(size_t)B_ * 32 * N_];  // colmean partials

// ---------------------------------------------------------------------------
// Helpers (baseline PTX only — ptxas targets sm_103, no 'a'-gated instrs)
// ---------------------------------------------------------------------------
__device__ __forceinline__ uint32_t su32(const void* p) {
    uint32_t a;
    asm("{ .reg .u64 t; cvta.to.shared.u64 t, %1; cvt.u32.u64 %0, t; }" : "=r"(a) : "l"(p));
    return a;
}
__device__ __forceinline__ void cp_async16(uint32_t dst, const void* src) {
    asm volatile("cp.async.cg.shared.global [%0], [%1], 16;" :: "r"(dst), "l"(src) : "memory");
}
__device__ __forceinline__ void cp_commit() {
    asm volatile("cp.async.commit_group;" ::: "memory");
}
__device__ __forceinline__ void cp_wait0() {
    asm volatile("cp.async.wait_group 0;" ::: "memory");
}
__device__ __forceinline__ void cp_wait1() {
    asm volatile("cp.async.wait_group 1;" ::: "memory");
}
__device__ __forceinline__ uint32_t f2tf(float f) {
    uint32_t r;
    asm("cvt.rna.tf32.f32 %0, %1;" : "=r"(r) : "f"(f));
    return r;
}
// 3xTF32 split: hi = rna(v); lo = v - hi kept as raw fp32 (tf32 HMMA reads
// only the tf32 bits of the register, so the low mantissa is truncated free).
__device__ __forceinline__ void split_tf(float v, uint32_t& hi, uint32_t& lo) {
    hi = f2tf(v);
    lo = __float_as_uint(v - __uint_as_float(hi));
}
__device__ __forceinline__ void mma_tf32(float* d, const uint32_t* a, const uint32_t* b) {
    asm volatile(
        "mma.sync.aligned.m16n8k8.row.col.f32.tf32.tf32.f32 "
        "{%0,%1,%2,%3}, {%4,%5,%6,%7}, {%8,%9}, {%0,%1,%2,%3};"
        : "+f"(d[0]), "+f"(d[1]), "+f"(d[2]), "+f"(d[3])
        : "r"(a[0]), "r"(a[1]), "r"(a[2]), "r"(a[3]), "r"(b[0]), "r"(b[1]));
}

// fast exp(t) for t <= 0: exp2 via degree-5 minimax poly on FMA pipe (no MUFU)
__device__ __forceinline__ float fast_exp_neg(float t) {
    float z = fmaxf(t * 1.4426950408889634f, -120.0f);
    float fi = floorf(z);
    float f = z - fi;
    float p =              0.00133335581f;
    p = fmaf(p, f,         0.00961812910f);
    p = fmaf(p, f,         0.0555041086f);
    p = fmaf(p, f,         0.240226462f);
    p = fmaf(p, f,         0.693147182f);
    p = fmaf(p, f,         1.0f);
    return p * __int_as_float(((int)fi + 127) << 23);
}

// smem float-index with XOR swizzle: row stride 32 floats (128B), k ^ (row&7)*4
#define SWZ(r, k) (((r) * 32) + ((k) ^ (((r) & 7) * 4)))

extern __shared__ float dynsm_f[];

// ---------------------------------------------------------------------------
// GEMM core: D[128 x 128] += A[128 x K] @ B[128 x K]^T  (3xTF32 HMMA, fp32 acc)
// A rows are M (K-contig, stride lda); B rows are N (K-contig, stride ldb).
// Dynamic smem: 3 stages x (A 16KB + B 16KB) = 96KB.
// 8 warps: wr = warp>>2 (2 row groups of 64), wc = warp&3 (4 col groups of 32).
// ---------------------------------------------------------------------------
__device__ __forceinline__ void gemm_core(
    const float* __restrict__ A, int lda,
    const float* __restrict__ Bm, int ldb,
    int nK, float acc[4][4][4])
{
    float* sm = dynsm_f;
    const int tid  = threadIdx.x;
    const int lr   = tid >> 3;         // 0..31
    const int lc4  = (tid & 7) * 4;    // 0,4,...,28
    const int lane = tid & 31, warp = tid >> 5;
    const int wr = warp >> 2, wc = warp & 3;
    const int g = lane >> 2, tg = lane & 3;

    auto issue = [&](int s, int kt) {
        const int k0 = kt * 32;
        float* sa = sm + s * 8192;
        float* sb = sa + 4096;
        #pragma unroll
        for (int p = 0; p < 4; ++p) {
            const int r = p * 32 + lr;
            cp_async16(su32(&sa[SWZ(r, lc4)]), &A [(size_t)r * lda + k0 + lc4]);
            cp_async16(su32(&sb[SWZ(r, lc4)]), &Bm[(size_t)r * ldb + k0 + lc4]);
        }
        cp_commit();
    };

    issue(0, 0);
    if (nK > 1) issue(1, 1);

    for (int kt = 0; kt < nK; ++kt) {
        const int s = kt % 3;
        if (kt + 1 < nK) cp_wait1(); else cp_wait0();
        __syncthreads();
        if (kt + 2 < nK) issue((kt + 2) % 3, kt + 2);

        const float* sa = sm + s * 8192;
        const float* sb = sa + 4096;
        #pragma unroll
        for (int k8 = 0; k8 < 4; ++k8) {
            const int kq = k8 * 8 + tg;
            uint32_t afh[4][4], afl[4][4], bfh[4][2], bfl[4][2];
            #pragma unroll
            for (int am = 0; am < 4; ++am) {
                const int r = wr * 64 + am * 16 + g;
                split_tf(sa[SWZ(r,     kq)],     afh[am][0], afl[am][0]);
                split_tf(sa[SWZ(r + 8, kq)],     afh[am][1], afl[am][1]);
                split_tf(sa[SWZ(r,     kq + 4)], afh[am][2], afl[am][2]);
                split_tf(sa[SWZ(r + 8, kq + 4)], afh[am][3], afl[am][3]);
            }
            #pragma unroll
            for (int bn = 0; bn < 4; ++bn) {
                const int rb = wc * 32 + bn * 8 + g;
                split_tf(sb[SWZ(rb, kq)],     bfh[bn][0], bfl[bn][0]);
                split_tf(sb[SWZ(rb, kq + 4)], bfh[bn][1], bfl[bn][1]);
            }
            // pass 1: hi*hi
            #pragma unroll
            for (int am = 0; am < 4; ++am)
                #pragma unroll
                for (int bn = 0; bn < 4; ++bn)
                    mma_tf32(acc[am][bn], afh[am], bfh[bn]);
            // pass 2: hi*lo
            #pragma unroll
            for (int am = 0; am < 4; ++am)
                #pragma unroll
                for (int bn = 0; bn < 4; ++bn)
                    mma_tf32(acc[am][bn], afh[am], bfl[bn]);
            // pass 3: lo*hi
            #pragma unroll
            for (int am = 0; am < 4; ++am)
                #pragma unroll
                for (int bn = 0; bn < 4; ++bn)
                    mma_tf32(acc[am][bn], afl[am], bfh[bn]);
        }
    }
}

// Epilogue: Out[r][c] = acc (+ bias_col[c]) (+ bias_row[r]); Out pre-offset to tile.
__device__ __forceinline__ void epi_store(
    float acc[4][4][4], float* __restrict__ Out, int ld,
    const float* __restrict__ bias_col, const float* __restrict__ bias_row)
{
    const int lane = threadIdx.x & 31, warp = threadIdx.x >> 5;
    const int wr = warp >> 2, wc = warp & 3;
    const int g = lane >> 2, tg = lane & 3;
    #pragma unroll
    for (int am = 0; am < 4; ++am) {
        const int r = wr * 64 + am * 16 + g;
        const float br0 = bias_row ? bias_row[r]     : 0.f;
        const float br1 = bias_row ? bias_row[r + 8] : 0.f;
        #pragma unroll
        for (int bn = 0; bn < 4; ++bn) {
            const int c = wc * 32 + bn * 8 + tg * 2;
            const float b0 = bias_col ? bias_col[c]     : 0.f;
            const float b1 = bias_col ? bias_col[c + 1] : 0.f;
            float2 v0 = { acc[am][bn][0] + b0 + br0, acc[am][bn][1] + b1 + br0 };
            float2 v1 = { acc[am][bn][2] + b0 + br1, acc[am][bn][3] + b1 + br1 };
            *reinterpret_cast<float2*>(&Out[(size_t)r       * ld + c]) = v0;
            *reinterpret_cast<float2*>(&Out[(size_t)(r + 8) * ld + c]) = v1;
        }
    }
}

// ---------------------------------------------------------------------------
// Kernels
// ---------------------------------------------------------------------------
__global__ __launch_bounds__(256) void transpose_x_kernel(const float* __restrict__ x)
{
    __shared__ float t[32][33];
    const int b = blockIdx.z, n0 = blockIdx.x * 32, c0 = blockIdx.y * 32;
    const int tx = threadIdx.x, ty = threadIdx.y;
    const float* X = x + (size_t)b * C_ * N_;
    float* XT = g_xt + (size_t)b * N_ * C_;
    #pragma unroll
    for (int i = 0; i < 4; ++i)
        t[ty + i * 8][tx] = X[(size_t)(c0 + ty + i * 8) * N_ + n0 + tx];
    __syncthreads();
    #pragma unroll
    for (int i = 0; i < 4; ++i)
        XT[(size_t)(n0 + ty + i * 8) * C_ + c0 + tx] = t[tx][ty + i * 8];
}

// f^T / g^T:  D[n][o] = xt[n][:] . W[o][:]   -> row-major write to ft/gt
__global__ __launch_bounds__(256, 2) void projfg_kernel(
    const float* __restrict__ Wf, const float* __restrict__ bf,
    const float* __restrict__ Wg, const float* __restrict__ bg)
{
    const int b = blockIdx.z, n0 = blockIdx.x * 128, ot = blockIdx.y;
    const float* A = g_xt + ((size_t)b * N_ + n0) * C_;
    const float* W; const float* bias; float* Out; int o0;
    if (ot < 2) { W = Wf + (size_t)(ot * 128) * C_;       bias = bf + ot * 128;       Out = g_ft + (size_t)b * N_ * HC_; o0 = ot * 128; }
    else        { W = Wg + (size_t)((ot - 2) * 128) * C_; bias = bg + (ot - 2) * 128; Out = g_gt + (size_t)b * N_ * HC_; o0 = (ot - 2) * 128; }

    float acc[4][4][4] = {};
    gemm_core(A, C_, W, C_, C_ / 32, acc);
    epi_store(acc, Out + (size_t)n0 * HC_ + o0, HC_, bias, nullptr);
}

// h:  D[c][n] = Wh[c][:] . xt[n][:]   -> row-major write to g_h
__global__ __launch_bounds__(256, 2) void projh_kernel(
    const float* __restrict__ Wh, const float* __restrict__ bh)
{
    const int b = blockIdx.z, n0 = blockIdx.x * 128, c0 = blockIdx.y * 128;
    const float* A = Wh + (size_t)c0 * C_;
    const float* Bm = g_xt + ((size_t)b * N_ + n0) * C_;

    float acc[4][4][4] = {};
    gemm_core(A, C_, Bm, C_, C_ / 32, acc);
    epi_store(acc, g_h + (size_t)b * C_ * N_ + (size_t)c0 * N_ + n0, N_, nullptr, bh + c0);
}

// energy: D[j][k] = ft[j][:] . gt[k][:]
__global__ __launch_bounds__(256, 2) void energy_kernel()
{
    const int b = blockIdx.z, k0 = blockIdx.x * 128, j0 = blockIdx.y * 128;
    const float* A  = g_ft + ((size_t)b * N_ + j0) * HC_;
    const float* Bm = g_gt + ((size_t)b * N_ + k0) * HC_;

    float acc[4][4][4] = {};
    gemm_core(A, HC_, Bm, HC_, HC_ / 32, acc);
    epi_store(acc, g_E + (size_t)b * N_ * N_ + (size_t)j0 * N_ + k0, N_, nullptr, nullptr);
}

// residual: D[c][j] = h[c][:] . corr[j][:]
__global__ __launch_bounds__(256, 2) void residual_kernel(float* __restrict__ out)
{
    const int b = blockIdx.z, j0 = blockIdx.x * 128, c0 = blockIdx.y * 128;
    const float* A  = g_h + (size_t)b * C_ * N_ + (size_t)c0 * N_;
    const float* Bm = g_E + (size_t)b * N_ * N_ + (size_t)j0 * N_;

    float acc[4][4][4] = {};
    gemm_core(A, N_, Bm, N_, N_ / 32, acc);
    epi_store(acc, out + (size_t)b * C_ * N_ + (size_t)c0 * N_ + j0, N_, nullptr, nullptr);
}

__global__ __launch_bounds__(256) void softmax_kernel()
{
    const int b = blockIdx.y;
    const int j = blockIdx.x;
    float* row = g_E + ((size_t)b * N_ + j) * N_;
    const int tid = threadIdx.x;

    float v[16];
    float m = -CUDART_INF_F;
    #pragma unroll
    for (int i = 0; i < 16; ++i) { v[i] = row[tid + i * 256]; m = fmaxf(m, v[i]); }

    __shared__ float red[8];
    #pragma unroll
    for (int o = 16; o; o >>= 1) m = fmaxf(m, __shfl_xor_sync(0xffffffffu, m, o));
    if ((tid & 31) == 0) red[tid >> 5] = m;
    __syncthreads();
    {
        float t = (tid < 8) ? red[tid] : -CUDART_INF_F;
        #pragma unroll
        for (int o = 4; o; o >>= 1) t = fmaxf(t, __shfl_xor_sync(0xffffffffu, t, o));
        if (tid == 0) red[0] = t;
    }
    __syncthreads();
    m = red[0];
    __syncthreads();

    float s = 0.f;
    #pragma unroll
    for (int i = 0; i < 16; ++i) { v[i] = fast_exp_neg(v[i] - m); s += v[i]; }
    #pragma unroll
    for (int o = 16; o; o >>= 1) s += __shfl_xor_sync(0xffffffffu, s, o);
    if ((tid & 31) == 0) red[tid >> 5] = s;
    __syncthreads();
    {
        float t = (tid < 8) ? red[tid] : 0.f;
        #pragma unroll
        for (int o = 4; o; o >>= 1) t += __shfl_xor_sync(0xffffffffu, t, o);
        if (tid == 0) red[0] = t;
    }
    __syncthreads();
    const float inv = 1.0f / red[0];

    #pragma unroll
    for (int i = 0; i < 16; ++i) row[tid + i * 256] = v[i] * inv;
}

__global__ __launch_bounds__(256) void colmean_part_kernel()
{
    const int b = blockIdx.z, jb = blockIdx.y;
    const int col = blockIdx.x * 256 + threadIdx.x;
    const float* E = g_E + (size_t)b * N_ * N_ + (size_t)jb * 128 * N_;
    float s = 0.f;
    #pragma unroll 8
    for (int j = 0; j < 128; ++j) s += E[(size_t)j * N_ + col];
    g_part[((size_t)b * 32 + jb) * N_ + col] = s;
}

__global__ __launch_bounds__(256) void colmean_final_kernel(float* __restrict__ out)
{
    const int b = blockIdx.y;
    const int col = blockIdx.x * 256 + threadIdx.x;
    float s = 0.f;
    #pragma unroll
    for (int p = 0; p < 32; ++p) s += g_part[((size_t)b * 32 + p) * N_ + col];
    out[(size_t)B_ * C_ * N_ + (size_t)b * N_ + col] = s * (1.0f / N_);
}

// ---------------------------------------------------------------------------
extern "C" void kernel_launch(void* const* d_in, const int* in_sizes, int n_in,
                              void* d_out, int out_size)
{
    const float* x  = (const float*)d_in[0];
    const float* Wf = (const float*)d_in[1];
    const float* bf = (const float*)d_in[2];
    const float* Wg = (const float*)d_in[3];
    const float* bg = (const float*)d_in[4];
    const float* Wh = (const float*)d_in[5];
    const float* bh = (const float*)d_in[6];
    float* out = (float*)d_out;

    const int SMEM = 98304;  // 3 stages x (16KB A + 16KB B)
    cudaFuncSetAttribute(projfg_kernel,   cudaFuncAttributeMaxDynamicSharedMemorySize, SMEM);
    cudaFuncSetAttribute(projh_kernel,    cudaFuncAttributeMaxDynamicSharedMemorySize, SMEM);
    cudaFuncSetAttribute(energy_kernel,   cudaFuncAttributeMaxDynamicSharedMemorySize, SMEM);
    cudaFuncSetAttribute(residual_kernel, cudaFuncAttributeMaxDynamicSharedMemorySize, SMEM);

    transpose_x_kernel<<<dim3(N_ / 32, C_ / 32, B_), dim3(32, 8)>>>(x);
    projfg_kernel<<<dim3(32, 4, B_), 256, SMEM>>>(Wf, bf, Wg, bg);
    projh_kernel<<<dim3(32, 4, B_), 256, SMEM>>>(Wh, bh);
    energy_kernel<<<dim3(32, 32, B_), 256, SMEM>>>();
    softmax_kernel<<<dim3(N_, B_), 256>>>();
    colmean_part_kernel<<<dim3(16, 32, B_), 256>>>();
    colmean_final_kernel<<<dim3(16, B_), 256>>>(out);
    residual_kernel<<<dim3(32, 4, B_), 256, SMEM>>>(out);
}

// round 7
// speedup vs baseline: 1.5009x; 1.2009x over previous
#include <cuda_runtime.h>
#include <math_constants.h>
#include <cstdint>

#define B_  4
#define C_  512
#define HC_ 256
#define N_  4096

// ---------------------------------------------------------------------------
// Device scratch
// ---------------------------------------------------------------------------
__device__ float g_xt[(size_t)B_ * N_ * C_];    // x^T: [b][n][c]
__device__ float g_ft[(size_t)B_ * N_ * HC_];   // f^T: [b][n][hc]
__device__ float g_gt[(size_t)B_ * N_ * HC_];   // g^T: [b][n][hc]
__device__ float g_h [(size_t)B_ * C_ * N_];    // h:   [b][c][n]
__device__ float g_E [(size_t)B_ * N_ * N_];    // energy; after softmax: corr (tf32-rounded)
__device__ float g_part[(size_t)B_ * 32 * N_];  // colmean partials

// ---------------------------------------------------------------------------
// Helpers (baseline PTX only — ptxas targets sm_103, no 'a'-gated instrs)
// ---------------------------------------------------------------------------
__device__ __forceinline__ uint32_t su32(const void* p) {
    uint32_t a;
    asm("{ .reg .u64 t; cvta.to.shared.u64 t, %1; cvt.u32.u64 %0, t; }" : "=r"(a) : "l"(p));
    return a;
}
__device__ __forceinline__ void cp_async16(uint32_t dst, const void* src) {
    asm volatile("cp.async.cg.shared.global [%0], [%1], 16;" :: "r"(dst), "l"(src) : "memory");
}
__device__ __forceinline__ void cp_commit() {
    asm volatile("cp.async.commit_group;" ::: "memory");
}
__device__ __forceinline__ void cp_wait0() {
    asm volatile("cp.async.wait_group 0;" ::: "memory");
}
__device__ __forceinline__ void cp_wait1() {
    asm volatile("cp.async.wait_group 1;" ::: "memory");
}
__device__ __forceinline__ uint32_t f2tf(float f) {
    uint32_t r;
    asm("cvt.rna.tf32.f32 %0, %1;" : "=r"(r) : "f"(f));
    return r;
}
// 3xTF32 split: hi = rna(v); lo = v - hi kept as raw fp32 (HMMA truncates lo
// to tf32 itself, which is fine: |lo| <= 2^-11 |v| so the residual is ~2^-24).
__device__ __forceinline__ void split_tf(float v, uint32_t& hi, uint32_t& lo) {
    hi = f2tf(v);
    lo = __float_as_uint(v - __uint_as_float(hi));
}
__device__ __forceinline__ void mma_tf32(float* d, const uint32_t* a, const uint32_t* b) {
    asm volatile(
        "mma.sync.aligned.m16n8k8.row.col.f32.tf32.tf32.f32 "
        "{%0,%1,%2,%3}, {%4,%5,%6,%7}, {%8,%9}, {%0,%1,%2,%3};"
        : "+f"(d[0]), "+f"(d[1]), "+f"(d[2]), "+f"(d[3])
        : "r"(a[0]), "r"(a[1]), "r"(a[2]), "r"(a[3]), "r"(b[0]), "r"(b[1]));
}

// fast exp(t) for t <= 0: exp2 via degree-5 minimax poly on FMA pipe (no MUFU)
__device__ __forceinline__ float fast_exp_neg(float t) {
    float z = fmaxf(t * 1.4426950408889634f, -120.0f);
    float fi = floorf(z);
    float f = z - fi;
    float p =              0.00133335581f;
    p = fmaf(p, f,         0.00961812910f);
    p = fmaf(p, f,         0.0555041086f);
    p = fmaf(p, f,         0.240226462f);
    p = fmaf(p, f,         0.693147182f);
    p = fmaf(p, f,         1.0f);
    return p * __int_as_float(((int)fi + 127) << 23);
}

// smem float-index with XOR swizzle: row stride 32 floats (128B), k ^ (row&7)*4
#define SWZ(r, k) (((r) * 32) + ((k) ^ (((r) & 7) * 4)))

extern __shared__ float dynsm_f[];

// ---------------------------------------------------------------------------
// GEMM core: D[128 x 128] += A[128 x K] @ B[128 x K]^T  (tf32 HMMA, fp32 acc)
// A rows are M (K-contig, stride lda); B rows are N (K-contig, stride ldb).
// SPLIT_B = true : full 3xTF32 (A and B split; passes hi*hi, hi*lo, lo*hi).
// SPLIT_B = false: B is already exactly tf32-representable; A split only
//                  (passes a_hi*b, a_lo*b) — 2/3 the MMA work, zero extra error.
// Dynamic smem: 3 stages x (A 16KB + B 16KB) = 96KB.
// 8 warps: wr = warp>>2 (2 row groups of 64), wc = warp&3 (4 col groups of 32).
// ---------------------------------------------------------------------------
template <bool SPLIT_B>
__device__ __forceinline__ void gemm_core(
    const float* __restrict__ A, int lda,
    const float* __restrict__ Bm, int ldb,
    int nK, float acc[4][4][4])
{
    float* sm = dynsm_f;
    const int tid  = threadIdx.x;
    const int lr   = tid >> 3;         // 0..31
    const int lc4  = (tid & 7) * 4;    // 0,4,...,28
    const int lane = tid & 31, warp = tid >> 5;
    const int wr = warp >> 2, wc = warp & 3;
    const int g = lane >> 2, tg = lane & 3;

    auto issue = [&](int s, int kt) {
        const int k0 = kt * 32;
        float* sa = sm + s * 8192;
        float* sb = sa + 4096;
        #pragma unroll
        for (int p = 0; p < 4; ++p) {
            const int r = p * 32 + lr;
            cp_async16(su32(&sa[SWZ(r, lc4)]), &A [(size_t)r * lda + k0 + lc4]);
            cp_async16(su32(&sb[SWZ(r, lc4)]), &Bm[(size_t)r * ldb + k0 + lc4]);
        }
        cp_commit();
    };

    issue(0, 0);
    if (nK > 1) issue(1, 1);

    for (int kt = 0; kt < nK; ++kt) {
        const int s = kt % 3;
        if (kt + 1 < nK) cp_wait1(); else cp_wait0();
        __syncthreads();
        if (kt + 2 < nK) issue((kt + 2) % 3, kt + 2);

        const float* sa = sm + s * 8192;
        const float* sb = sa + 4096;
        #pragma unroll
        for (int k8 = 0; k8 < 4; ++k8) {
            const int kq = k8 * 8 + tg;
            uint32_t afh[4][4], afl[4][4], bfh[4][2], bfl[4][2];
            #pragma unroll
            for (int am = 0; am < 4; ++am) {
                const int r = wr * 64 + am * 16 + g;
                split_tf(sa[SWZ(r,     kq)],     afh[am][0], afl[am][0]);
                split_tf(sa[SWZ(r + 8, kq)],     afh[am][1], afl[am][1]);
                split_tf(sa[SWZ(r,     kq + 4)], afh[am][2], afl[am][2]);
                split_tf(sa[SWZ(r + 8, kq + 4)], afh[am][3], afl[am][3]);
            }
            #pragma unroll
            for (int bn = 0; bn < 4; ++bn) {
                const int rb = wc * 32 + bn * 8 + g;
                if (SPLIT_B) {
                    split_tf(sb[SWZ(rb, kq)],     bfh[bn][0], bfl[bn][0]);
                    split_tf(sb[SWZ(rb, kq + 4)], bfh[bn][1], bfl[bn][1]);
                } else {
                    bfh[bn][0] = __float_as_uint(sb[SWZ(rb, kq)]);
                    bfh[bn][1] = __float_as_uint(sb[SWZ(rb, kq + 4)]);
                }
            }
            // pass 1: a_hi * b_hi
            #pragma unroll
            for (int am = 0; am < 4; ++am)
                #pragma unroll
                for (int bn = 0; bn < 4; ++bn)
                    mma_tf32(acc[am][bn], afh[am], bfh[bn]);
            // pass 2 (split B only): a_hi * b_lo
            if (SPLIT_B) {
                #pragma unroll
                for (int am = 0; am < 4; ++am)
                    #pragma unroll
                    for (int bn = 0; bn < 4; ++bn)
                        mma_tf32(acc[am][bn], afh[am], bfl[bn]);
            }
            // pass 3: a_lo * b_hi
            #pragma unroll
            for (int am = 0; am < 4; ++am)
                #pragma unroll
                for (int bn = 0; bn < 4; ++bn)
                    mma_tf32(acc[am][bn], afl[am], bfh[bn]);
        }
    }
}

// Epilogue: Out[r][c] = acc (+ bias_col[c]) (+ bias_row[r]); Out pre-offset to tile.
__device__ __forceinline__ void epi_store(
    float acc[4][4][4], float* __restrict__ Out, int ld,
    const float* __restrict__ bias_col, const float* __restrict__ bias_row)
{
    const int lane = threadIdx.x & 31, warp = threadIdx.x >> 5;
    const int wr = warp >> 2, wc = warp & 3;
    const int g = lane >> 2, tg = lane & 3;
    #pragma unroll
    for (int am = 0; am < 4; ++am) {
        const int r = wr * 64 + am * 16 + g;
        const float br0 = bias_row ? bias_row[r]     : 0.f;
        const float br1 = bias_row ? bias_row[r + 8] : 0.f;
        #pragma unroll
        for (int bn = 0; bn < 4; ++bn) {
            const int c = wc * 32 + bn * 8 + tg * 2;
            const float b0 = bias_col ? bias_col[c]     : 0.f;
            const float b1 = bias_col ? bias_col[c + 1] : 0.f;
            float2 v0 = { acc[am][bn][0] + b0 + br0, acc[am][bn][1] + b1 + br0 };
            float2 v1 = { acc[am][bn][2] + b0 + br1, acc[am][bn][3] + b1 + br1 };
            *reinterpret_cast<float2*>(&Out[(size_t)r       * ld + c]) = v0;
            *reinterpret_cast<float2*>(&Out[(size_t)(r + 8) * ld + c]) = v1;
        }
    }
}

// ---------------------------------------------------------------------------
// Kernels
// ---------------------------------------------------------------------------
__global__ __launch_bounds__(256) void transpose_x_kernel(const float* __restrict__ x)
{
    __shared__ float t[32][33];
    const int b = blockIdx.z, n0 = blockIdx.x * 32, c0 = blockIdx.y * 32;
    const int tx = threadIdx.x, ty = threadIdx.y;
    const float* X = x + (size_t)b * C_ * N_;
    float* XT = g_xt + (size_t)b * N_ * C_;
    #pragma unroll
    for (int i = 0; i < 4; ++i)
        t[ty + i * 8][tx] = X[(size_t)(c0 + ty + i * 8) * N_ + n0 + tx];
    __syncthreads();
    #pragma unroll
    for (int i = 0; i < 4; ++i)
        XT[(size_t)(n0 + ty + i * 8) * C_ + c0 + tx] = t[tx][ty + i * 8];
}

// f^T / g^T:  D[n][o] = xt[n][:] . W[o][:]   -> row-major write to ft/gt
__global__ __launch_bounds__(256, 2) void projfg_kernel(
    const float* __restrict__ Wf, const float* __restrict__ bf,
    const float* __restrict__ Wg, const float* __restrict__ bg)
{
    const int b = blockIdx.z, n0 = blockIdx.x * 128, ot = blockIdx.y;
    const float* A = g_xt + ((size_t)b * N_ + n0) * C_;
    const float* W; const float* bias; float* Out; int o0;
    if (ot < 2) { W = Wf + (size_t)(ot * 128) * C_;       bias = bf + ot * 128;       Out = g_ft + (size_t)b * N_ * HC_; o0 = ot * 128; }
    else        { W = Wg + (size_t)((ot - 2) * 128) * C_; bias = bg + (ot - 2) * 128; Out = g_gt + (size_t)b * N_ * HC_; o0 = (ot - 2) * 128; }

    float acc[4][4][4] = {};
    gemm_core<true>(A, C_, W, C_, C_ / 32, acc);
    epi_store(acc, Out + (size_t)n0 * HC_ + o0, HC_, bias, nullptr);
}

// h:  D[c][n] = Wh[c][:] . xt[n][:]   -> row-major write to g_h
__global__ __launch_bounds__(256, 2) void projh_kernel(
    const float* __restrict__ Wh, const float* __restrict__ bh)
{
    const int b = blockIdx.z, n0 = blockIdx.x * 128, c0 = blockIdx.y * 128;
    const float* A = Wh + (size_t)c0 * C_;
    const float* Bm = g_xt + ((size_t)b * N_ + n0) * C_;

    float acc[4][4][4] = {};
    gemm_core<true>(A, C_, Bm, C_, C_ / 32, acc);
    epi_store(acc, g_h + (size_t)b * C_ * N_ + (size_t)c0 * N_ + n0, N_, nullptr, bh + c0);
}

// energy: D[j][k] = ft[j][:] . gt[k][:]
__global__ __launch_bounds__(256, 2) void energy_kernel()
{
    const int b = blockIdx.z, k0 = blockIdx.x * 128, j0 = blockIdx.y * 128;
    const float* A  = g_ft + ((size_t)b * N_ + j0) * HC_;
    const float* Bm = g_gt + ((size_t)b * N_ + k0) * HC_;

    float acc[4][4][4] = {};
    gemm_core<true>(A, HC_, Bm, HC_, HC_ / 32, acc);
    epi_store(acc, g_E + (size_t)b * N_ * N_ + (size_t)j0 * N_ + k0, N_, nullptr, nullptr);
}

// residual: D[c][j] = h[c][:] . corr[j][:]
// corr is tf32-rounded by softmax -> 2-pass GEMM (B needs no split).
__global__ __launch_bounds__(256, 2) void residual_kernel(float* __restrict__ out)
{
    const int b = blockIdx.z, j0 = blockIdx.x * 128, c0 = blockIdx.y * 128;
    const float* A  = g_h + (size_t)b * C_ * N_ + (size_t)c0 * N_;
    const float* Bm = g_E + (size_t)b * N_ * N_ + (size_t)j0 * N_;

    float acc[4][4][4] = {};
    gemm_core<false>(A, N_, Bm, N_, N_ / 32, acc);
    epi_store(acc, out + (size_t)b * C_ * N_ + (size_t)c0 * N_ + j0, N_, nullptr, nullptr);
}

__global__ __launch_bounds__(256) void softmax_kernel()
{
    const int b = blockIdx.y;
    const int j = blockIdx.x;
    float* row = g_E + ((size_t)b * N_ + j) * N_;
    const int tid = threadIdx.x;

    float v[16];
    float m = -CUDART_INF_F;
    #pragma unroll
    for (int i = 0; i < 16; ++i) { v[i] = row[tid + i * 256]; m = fmaxf(m, v[i]); }

    __shared__ float red[8];
    #pragma unroll
    for (int o = 16; o; o >>= 1) m = fmaxf(m, __shfl_xor_sync(0xffffffffu, m, o));
    if ((tid & 31) == 0) red[tid >> 5] = m;
    __syncthreads();
    {
        float t = (tid < 8) ? red[tid] : -CUDART_INF_F;
        #pragma unroll
        for (int o = 4; o; o >>= 1) t = fmaxf(t, __shfl_xor_sync(0xffffffffu, t, o));
        if (tid == 0) red[0] = t;
    }
    __syncthreads();
    m = red[0];
    __syncthreads();

    float s = 0.f;
    #pragma unroll
    for (int i = 0; i < 16; ++i) { v[i] = fast_exp_neg(v[i] - m); s += v[i]; }
    #pragma unroll
    for (int o = 16; o; o >>= 1) s += __shfl_xor_sync(0xffffffffu, s, o);
    if ((tid & 31) == 0) red[tid >> 5] = s;
    __syncthreads();
    {
        float t = (tid < 8) ? red[tid] : 0.f;
        #pragma unroll
        for (int o = 4; o; o >>= 1) t += __shfl_xor_sync(0xffffffffu, t, o);
        if (tid == 0) red[0] = t;
    }
    __syncthreads();
    const float inv = 1.0f / red[0];

    // Write corr rounded to tf32 so the residual GEMM can run 2-pass exactly.
    #pragma unroll
    for (int i = 0; i < 16; ++i)
        row[tid + i * 256] = __uint_as_float(f2tf(v[i] * inv));
}

__global__ __launch_bounds__(256) void colmean_part_kernel()
{
    const int b = blockIdx.z, jb = blockIdx.y;
    const int col = blockIdx.x * 256 + threadIdx.x;
    const float* E = g_E + (size_t)b * N_ * N_ + (size_t)jb * 128 * N_;
    float s = 0.f;
    #pragma unroll 8
    for (int j = 0; j < 128; ++j) s += E[(size_t)j * N_ + col];
    g_part[((size_t)b * 32 + jb) * N_ + col] = s;
}

__global__ __launch_bounds__(256) void colmean_final_kernel(float* __restrict__ out)
{
    const int b = blockIdx.y;
    const int col = blockIdx.x * 256 + threadIdx.x;
    float s = 0.f;
    #pragma unroll
    for (int p = 0; p < 32; ++p) s += g_part[((size_t)b * 32 + p) * N_ + col];
    out[(size_t)B_ * C_ * N_ + (size_t)b * N_ + col] = s * (1.0f / N_);
}

// ---------------------------------------------------------------------------
extern "C" void kernel_launch(void* const* d_in, const int* in_sizes, int n_in,
                              void* d_out, int out_size)
{
    const float* x  = (const float*)d_in[0];
    const float* Wf = (const float*)d_in[1];
    const float* bf = (const float*)d_in[2];
    const float* Wg = (const float*)d_in[3];
    const float* bg = (const float*)d_in[4];
    const float* Wh = (const float*)d_in[5];
    const float* bh = (const float*)d_in[6];
    float* out = (float*)d_out;

    const int SMEM = 98304;  // 3 stages x (16KB A + 16KB B)
    cudaFuncSetAttribute(projfg_kernel,   cudaFuncAttributeMaxDynamicSharedMemorySize, SMEM);
    cudaFuncSetAttribute(projh_kernel,    cudaFuncAttributeMaxDynamicSharedMemorySize, SMEM);
    cudaFuncSetAttribute(energy_kernel,   cudaFuncAttributeMaxDynamicSharedMemorySize, SMEM);
    cudaFuncSetAttribute(residual_kernel, cudaFuncAttributeMaxDynamicSharedMemorySize, SMEM);

    transpose_x_kernel<<<dim3(N_ / 32, C_ / 32, B_), dim3(32, 8)>>>(x);
    projfg_kernel<<<dim3(32, 4, B_), 256, SMEM>>>(Wf, bf, Wg, bg);
    projh_kernel<<<dim3(32, 4, B_), 256, SMEM>>>(Wh, bh);
    energy_kernel<<<dim3(32, 32, B_), 256, SMEM>>>();
    softmax_kernel<<<dim3(N_, B_), 256>>>();
    colmean_part_kernel<<<dim3(16, 32, B_), 256>>>();
    colmean_final_kernel<<<dim3(16, B_), 256>>>(out);
    residual_kernel<<<dim3(32, 4, B_), 256, SMEM>>>(out);
}

// round 8
// speedup vs baseline: 1.5424x; 1.0277x over previous
#include <cuda_runtime.h>
#include <math_constants.h>
#include <cstdint>

#define B_  4
#define C_  512
#define HC_ 256
#define N_  4096

// ---------------------------------------------------------------------------
// K-group permutation: within each 8-wide K group, position p holds
// k = (0,4,1,5,2,6,3,7)[p] so that fragment pairs (k, k+4) are adjacent.
// perm8(k):  value k -> stored position ; iperm8(p): position -> k.
// ---------------------------------------------------------------------------
__host__ __device__ __forceinline__ int perm8(int q)  { return ((q & 3) << 1) | (q >> 2); }
__device__ __forceinline__ int permpos(int c) { return (c & ~7) | perm8(c & 7); }

// ---------------------------------------------------------------------------
// Device scratch (all K-contraction dims stored permuted)
// ---------------------------------------------------------------------------
__device__ float g_xt[(size_t)B_ * N_ * C_];    // x^T: [b][n][c-perm]
__device__ float g_Wp[(size_t)(HC_ + HC_ + C_) * C_]; // Wf|Wg|Wh, [o][c-perm]
__device__ float g_ft[(size_t)B_ * N_ * HC_];   // f^T: [b][n][hc-perm]
__device__ float g_gt[(size_t)B_ * N_ * HC_];   // g^T: [b][n][hc-perm]
__device__ float g_h [(size_t)B_ * C_ * N_];    // h:   [b][c][n-perm]
__device__ float g_E [(size_t)B_ * N_ * N_];    // energy/corr [b][j][k-perm]
__device__ float g_part[(size_t)B_ * 32 * N_];  // colmean partials (positions)

// ---------------------------------------------------------------------------
// Helpers (baseline PTX only — ptxas targets sm_103, no 'a'-gated instrs)
// ---------------------------------------------------------------------------
__device__ __forceinline__ uint32_t su32(const void* p) {
    uint32_t a;
    asm("{ .reg .u64 t; cvta.to.shared.u64 t, %1; cvt.u32.u64 %0, t; }" : "=r"(a) : "l"(p));
    return a;
}
__device__ __forceinline__ void cp_async16(uint32_t dst, const void* src) {
    asm volatile("cp.async.cg.shared.global [%0], [%1], 16;" :: "r"(dst), "l"(src) : "memory");
}
__device__ __forceinline__ void cp_commit() {
    asm volatile("cp.async.commit_group;" ::: "memory");
}
__device__ __forceinline__ void cp_wait0() {
    asm volatile("cp.async.wait_group 0;" ::: "memory");
}
__device__ __forceinline__ void cp_wait1() {
    asm volatile("cp.async.wait_group 1;" ::: "memory");
}
__device__ __forceinline__ uint32_t f2tf(float f) {
    uint32_t r;
    asm("cvt.rna.tf32.f32 %0, %1;" : "=r"(r) : "f"(f));
    return r;
}
// Truncation-based 3xTF32 split: hi = top tf32 bits (LOP3), lo = v - hi (exact).
// HMMA itself truncates lo's low mantissa; dropped term ~2^-24 relative.
__device__ __forceinline__ void split_m(float v, uint32_t& hi, uint32_t& lo) {
    hi = __float_as_uint(v) & 0xFFFFE000u;
    lo = __float_as_uint(v - __uint_as_float(hi));
}
__device__ __forceinline__ void mma_tf32(float* d, const uint32_t* a, const uint32_t* b) {
    asm volatile(
        "mma.sync.aligned.m16n8k8.row.col.f32.tf32.tf32.f32 "
        "{%0,%1,%2,%3}, {%4,%5,%6,%7}, {%8,%9}, {%0,%1,%2,%3};"
        : "+f"(d[0]), "+f"(d[1]), "+f"(d[2]), "+f"(d[3])
        : "r"(a[0]), "r"(a[1]), "r"(a[2]), "r"(a[3]), "r"(b[0]), "r"(b[1]));
}

// fast exp(t) for t <= 0: exp2 via degree-5 minimax poly on FMA pipe (no MUFU)
__device__ __forceinline__ float fast_exp_neg(float t) {
    float z = fmaxf(t * 1.4426950408889634f, -120.0f);
    float fi = floorf(z);
    float f = z - fi;
    float p =              0.00133335581f;
    p = fmaf(p, f,         0.00961812910f);
    p = fmaf(p, f,         0.0555041086f);
    p = fmaf(p, f,         0.240226462f);
    p = fmaf(p, f,         0.693147182f);
    p = fmaf(p, f,         1.0f);
    return p * __int_as_float(((int)fi + 127) << 23);
}

// smem float-index with XOR swizzle: row stride 32 floats (128B), 16B chunks
#define SWZ(r, k) (((r) * 32) + ((k) ^ (((r) & 7) * 4)))

extern __shared__ float dynsm_f[];

// ---------------------------------------------------------------------------
// GEMM core: D[128 x 128] += A[128 x K] @ B[128 x K]^T  (tf32 HMMA, fp32 acc)
// A, B K-contig with PERMUTED k-groups; fragment pairs load as LDS.64.
// SPLIT_B = true : full 3xTF32; false: B exactly tf32 -> 2-pass.
// smem: 3 stages x (A 16KB + B 16KB) = 96KB.
// ---------------------------------------------------------------------------
template <bool SPLIT_B>
__device__ __forceinline__ void gemm_core(
    const float* __restrict__ A, int lda,
    const float* __restrict__ Bm, int ldb,
    int nK, float acc[4][4][4])
{
    float* sm = dynsm_f;
    const int tid  = threadIdx.x;
    const int lr   = tid >> 3;         // 0..31
    const int lc4  = (tid & 7) * 4;    // 0,4,...,28
    const int lane = tid & 31, warp = tid >> 5;
    const int wr = warp >> 2, wc = warp & 3;
    const int g = lane >> 2, tg = lane & 3;
    // fragment pair (k, k+4) of group k8 lives at chunk (2*k8 | tg>>1),
    // float offset (tg&1)*2 within the chunk
    const int fchunk = tg >> 1;
    const int foff   = (tg & 1) << 1;

    auto issue = [&](int s, int kt) {
        const int k0 = kt * 32;
        float* sa = sm + s * 8192;
        float* sb = sa + 4096;
        #pragma unroll
        for (int p = 0; p < 4; ++p) {
            const int r = p * 32 + lr;
            cp_async16(su32(&sa[SWZ(r, lc4)]), &A [(size_t)r * lda + k0 + lc4]);
            cp_async16(su32(&sb[SWZ(r, lc4)]), &Bm[(size_t)r * ldb + k0 + lc4]);
        }
        cp_commit();
    };

    issue(0, 0);
    if (nK > 1) issue(1, 1);

    for (int kt = 0; kt < nK; ++kt) {
        const int s = kt % 3;
        if (kt + 1 < nK) cp_wait1(); else cp_wait0();
        __syncthreads();
        if (kt + 2 < nK) issue((kt + 2) % 3, kt + 2);

        const float* sa = sm + s * 8192;
        const float* sb = sa + 4096;
        #pragma unroll
        for (int k8 = 0; k8 < 4; ++k8) {
            const int chunk = (k8 << 1) | fchunk;
            uint32_t afh[4][4], afl[4][4], bfh[4][2], bfl[4][2];
            #pragma unroll
            for (int am = 0; am < 4; ++am) {
                const int r0 = wr * 64 + am * 16 + g;
                const int r1 = r0 + 8;
                float2 p0 = *reinterpret_cast<const float2*>(
                    &sa[r0 * 32 + ((chunk ^ (r0 & 7)) << 2) + foff]);
                float2 p1 = *reinterpret_cast<const float2*>(
                    &sa[r1 * 32 + ((chunk ^ (r1 & 7)) << 2) + foff]);
                split_m(p0.x, afh[am][0], afl[am][0]);
                split_m(p1.x, afh[am][1], afl[am][1]);
                split_m(p0.y, afh[am][2], afl[am][2]);
                split_m(p1.y, afh[am][3], afl[am][3]);
            }
            #pragma unroll
            for (int bn = 0; bn < 4; ++bn) {
                const int rb = wc * 32 + bn * 8 + g;
                float2 q = *reinterpret_cast<const float2*>(
                    &sb[rb * 32 + ((chunk ^ (rb & 7)) << 2) + foff]);
                if (SPLIT_B) {
                    split_m(q.x, bfh[bn][0], bfl[bn][0]);
                    split_m(q.y, bfh[bn][1], bfl[bn][1]);
                } else {
                    bfh[bn][0] = __float_as_uint(q.x);
                    bfh[bn][1] = __float_as_uint(q.y);
                }
            }
            // pass 1: a_hi * b_hi
            #pragma unroll
            for (int am = 0; am < 4; ++am)
                #pragma unroll
                for (int bn = 0; bn < 4; ++bn)
                    mma_tf32(acc[am][bn], afh[am], bfh[bn]);
            // pass 2 (split B only): a_hi * b_lo
            if (SPLIT_B) {
                #pragma unroll
                for (int am = 0; am < 4; ++am)
                    #pragma unroll
                    for (int bn = 0; bn < 4; ++bn)
                        mma_tf32(acc[am][bn], afh[am], bfl[bn]);
            }
            // pass 3: a_lo * b_hi
            #pragma unroll
            for (int am = 0; am < 4; ++am)
                #pragma unroll
                for (int bn = 0; bn < 4; ++bn)
                    mma_tf32(acc[am][bn], afl[am], bfh[bn]);
        }
    }
}

// Epilogue (natural columns): Out[r][c] = acc (+ biases). Used by residual.
__device__ __forceinline__ void epi_store(
    float acc[4][4][4], float* __restrict__ Out, int ld,
    const float* __restrict__ bias_col, const float* __restrict__ bias_row)
{
    const int lane = threadIdx.x & 31, warp = threadIdx.x >> 5;
    const int wr = warp >> 2, wc = warp & 3;
    const int g = lane >> 2, tg = lane & 3;
    #pragma unroll
    for (int am = 0; am < 4; ++am) {
        const int r = wr * 64 + am * 16 + g;
        const float br0 = bias_row ? bias_row[r]     : 0.f;
        const float br1 = bias_row ? bias_row[r + 8] : 0.f;
        #pragma unroll
        for (int bn = 0; bn < 4; ++bn) {
            const int c = wc * 32 + bn * 8 + tg * 2;
            const float b0 = bias_col ? bias_col[c]     : 0.f;
            const float b1 = bias_col ? bias_col[c + 1] : 0.f;
            float2 v0 = { acc[am][bn][0] + b0 + br0, acc[am][bn][1] + b1 + br0 };
            float2 v1 = { acc[am][bn][2] + b0 + br1, acc[am][bn][3] + b1 + br1 };
            *reinterpret_cast<float2*>(&Out[(size_t)r       * ld + c]) = v0;
            *reinterpret_cast<float2*>(&Out[(size_t)(r + 8) * ld + c]) = v1;
        }
    }
}

// Epilogue (permuted columns): value for column c stored at permpos(c).
// Used by all producers whose column dim is a downstream contraction dim.
__device__ __forceinline__ void epi_store_perm(
    float acc[4][4][4], float* __restrict__ Out, int ld,
    const float* __restrict__ bias_col, const float* __restrict__ bias_row)
{
    const int lane = threadIdx.x & 31, warp = threadIdx.x >> 5;
    const int wr = warp >> 2, wc = warp & 3;
    const int g = lane >> 2, tg = lane & 3;
    #pragma unroll
    for (int am = 0; am < 4; ++am) {
        const int r = wr * 64 + am * 16 + g;
        const float br0 = bias_row ? bias_row[r]     : 0.f;
        const float br1 = bias_row ? bias_row[r + 8] : 0.f;
        #pragma unroll
        for (int bn = 0; bn < 4; ++bn) {
            const int c = wc * 32 + bn * 8 + tg * 2;
            const float b0 = bias_col ? bias_col[c]     : 0.f;
            const float b1 = bias_col ? bias_col[c + 1] : 0.f;
            const int p0 = (c & ~7) | perm8(c & 7);
            const int p1 = (c & ~7) | perm8((c & 7) + 1);
            Out[(size_t)r       * ld + p0] = acc[am][bn][0] + b0 + br0;
            Out[(size_t)r       * ld + p1] = acc[am][bn][1] + b1 + br0;
            Out[(size_t)(r + 8) * ld + p0] = acc[am][bn][2] + b0 + br1;
            Out[(size_t)(r + 8) * ld + p1] = acc[am][bn][3] + b1 + br1;
        }
    }
}

// ---------------------------------------------------------------------------
// Producers
// ---------------------------------------------------------------------------
__global__ __launch_bounds__(256) void permute_w_kernel(
    const float* __restrict__ Wf, const float* __restrict__ Wg,
    const float* __restrict__ Wh)
{
    const int i = blockIdx.x * 256 + threadIdx.x;
    const int NW = (HC_ + HC_ + C_) * C_;
    if (i >= NW) return;
    float v;
    if (i < HC_ * C_)           v = Wf[i];
    else if (i < 2 * HC_ * C_)  v = Wg[i - HC_ * C_];
    else                        v = Wh[i - 2 * HC_ * C_];
    const int o = i / C_, c = i % C_;
    g_Wp[(size_t)o * C_ + permpos(c)] = v;
}

__global__ __launch_bounds__(256) void transpose_x_kernel(const float* __restrict__ x)
{
    __shared__ float t[32][33];
    const int b = blockIdx.z, n0 = blockIdx.x * 32, c0 = blockIdx.y * 32;
    const int tx = threadIdx.x, ty = threadIdx.y;
    const float* X = x + (size_t)b * C_ * N_;
    float* XT = g_xt + (size_t)b * N_ * C_;
    #pragma unroll
    for (int i = 0; i < 4; ++i)
        t[ty + i * 8][tx] = X[(size_t)(c0 + ty + i * 8) * N_ + n0 + tx];
    __syncthreads();
    const int cp = c0 + permpos(tx);
    #pragma unroll
    for (int i = 0; i < 4; ++i)
        XT[(size_t)(n0 + ty + i * 8) * C_ + cp] = t[tx][ty + i * 8];
}

// ---------------------------------------------------------------------------
// GEMM kernels
// ---------------------------------------------------------------------------
// f^T / g^T:  D[n][o] = xt[n][:] . W[o][:] -> [n][o-perm] (o is energy's K)
__global__ __launch_bounds__(256, 2) void projfg_kernel(
    const float* __restrict__ bf, const float* __restrict__ bg)
{
    const int b = blockIdx.z, n0 = blockIdx.x * 128, ot = blockIdx.y;
    const float* A = g_xt + ((size_t)b * N_ + n0) * C_;
    const float* W; const float* bias; float* Out; int o0;
    if (ot < 2) { W = g_Wp + (size_t)(ot * 128) * C_;             bias = bf + ot * 128;       Out = g_ft + (size_t)b * N_ * HC_; o0 = ot * 128; }
    else        { W = g_Wp + (size_t)(HC_ + (ot - 2) * 128) * C_; bias = bg + (ot - 2) * 128; Out = g_gt + (size_t)b * N_ * HC_; o0 = (ot - 2) * 128; }

    float acc[4][4][4] = {};
    gemm_core<true>(A, C_, W, C_, C_ / 32, acc);
    epi_store_perm(acc, Out + (size_t)n0 * HC_ + o0, HC_, bias, nullptr);
}

// h:  D[c][n] = Wh[c][:] . xt[n][:] -> [c][n-perm] (n is residual's K)
__global__ __launch_bounds__(256, 2) void projh_kernel(const float* __restrict__ bh)
{
    const int b = blockIdx.z, n0 = blockIdx.x * 128, c0 = blockIdx.y * 128;
    const float* A  = g_Wp + (size_t)(2 * HC_ + c0) * C_;
    const float* Bm = g_xt + ((size_t)b * N_ + n0) * C_;

    float acc[4][4][4] = {};
    gemm_core<true>(A, C_, Bm, C_, C_ / 32, acc);
    epi_store_perm(acc, g_h + (size_t)b * C_ * N_ + (size_t)c0 * N_ + n0, N_, nullptr, bh + c0);
}

// energy: D[j][k] = ft[j][:] . gt[k][:] -> [j][k-perm] (k is residual's K)
__global__ __launch_bounds__(256, 2) void energy_kernel()
{
    const int b = blockIdx.z, k0 = blockIdx.x * 128, j0 = blockIdx.y * 128;
    const float* A  = g_ft + ((size_t)b * N_ + j0) * HC_;
    const float* Bm = g_gt + ((size_t)b * N_ + k0) * HC_;

    float acc[4][4][4] = {};
    gemm_core<true>(A, HC_, Bm, HC_, HC_ / 32, acc);
    epi_store_perm(acc, g_E + (size_t)b * N_ * N_ + (size_t)j0 * N_ + k0, N_, nullptr, nullptr);
}

// residual: D[c][j] = h[c][:] . corr[j][:]  (corr tf32-rounded -> 2-pass)
__global__ __launch_bounds__(256, 2) void residual_kernel(float* __restrict__ out)
{
    const int b = blockIdx.z, j0 = blockIdx.x * 128, c0 = blockIdx.y * 128;
    const float* A  = g_h + (size_t)b * C_ * N_ + (size_t)c0 * N_;
    const float* Bm = g_E + (size_t)b * N_ * N_ + (size_t)j0 * N_;

    float acc[4][4][4] = {};
    gemm_core<false>(A, N_, Bm, N_, N_ / 32, acc);
    epi_store(acc, out + (size_t)b * C_ * N_ + (size_t)c0 * N_ + j0, N_, nullptr, nullptr);
}

// ---------------------------------------------------------------------------
// Softmax: elementwise over permuted row (permutation-invariant reductions)
// ---------------------------------------------------------------------------
__global__ __launch_bounds__(256) void softmax_kernel()
{
    const int b = blockIdx.y;
    const int j = blockIdx.x;
    float* row = g_E + ((size_t)b * N_ + j) * N_;
    const int tid = threadIdx.x;

    float v[16];
    float m = -CUDART_INF_F;
    #pragma unroll
    for (int i = 0; i < 16; ++i) { v[i] = row[tid + i * 256]; m = fmaxf(m, v[i]); }

    __shared__ float red[8];
    #pragma unroll
    for (int o = 16; o; o >>= 1) m = fmaxf(m, __shfl_xor_sync(0xffffffffu, m, o));
    if ((tid & 31) == 0) red[tid >> 5] = m;
    __syncthreads();
    {
        float t = (tid < 8) ? red[tid] : -CUDART_INF_F;
        #pragma unroll
        for (int o = 4; o; o >>= 1) t = fmaxf(t, __shfl_xor_sync(0xffffffffu, t, o));
        if (tid == 0) red[0] = t;
    }
    __syncthreads();
    m = red[0];
    __syncthreads();

    float s = 0.f;
    #pragma unroll
    for (int i = 0; i < 16; ++i) { v[i] = fast_exp_neg(v[i] - m); s += v[i]; }
    #pragma unroll
    for (int o = 16; o; o >>= 1) s += __shfl_xor_sync(0xffffffffu, s, o);
    if ((tid & 31) == 0) red[tid >> 5] = s;
    __syncthreads();
    {
        float t = (tid < 8) ? red[tid] : 0.f;
        #pragma unroll
        for (int o = 4; o; o >>= 1) t += __shfl_xor_sync(0xffffffffu, t, o);
        if (tid == 0) red[0] = t;
    }
    __syncthreads();
    const float inv = 1.0f / red[0];

    // Round to tf32 so the residual GEMM runs 2-pass exactly.
    #pragma unroll
    for (int i = 0; i < 16; ++i)
        row[tid + i * 256] = __uint_as_float(f2tf(v[i] * inv));
}

// ---------------------------------------------------------------------------
// Column mean (columns are permuted positions; final un-permutes the index)
// ---------------------------------------------------------------------------
__global__ __launch_bounds__(256) void colmean_part_kernel()
{
    const int b = blockIdx.z, jb = blockIdx.y;
    const int col = blockIdx.x * 256 + threadIdx.x;
    const float* E = g_E + (size_t)b * N_ * N_ + (size_t)jb * 128 * N_;
    float s = 0.f;
    #pragma unroll 8
    for (int j = 0; j < 128; ++j) s += E[(size_t)j * N_ + col];
    g_part[((size_t)b * 32 + jb) * N_ + col] = s;
}

__global__ __launch_bounds__(256) void colmean_final_kernel(float* __restrict__ out)
{
    const int b = blockIdx.y;
    const int col = blockIdx.x * 256 + threadIdx.x;  // permuted position
    float s = 0.f;
    #pragma unroll
    for (int p = 0; p < 32; ++p) s += g_part[((size_t)b * 32 + p) * N_ + col];
    const int m = (col & ~7) | ((col & 7) >> 1) | ((col & 1) << 2);  // iperm8
    out[(size_t)B_ * C_ * N_ + (size_t)b * N_ + m] = s * (1.0f / N_);
}

// ---------------------------------------------------------------------------
extern "C" void kernel_launch(void* const* d_in, const int* in_sizes, int n_in,
                              void* d_out, int out_size)
{
    const float* x  = (const float*)d_in[0];
    const float* Wf = (const float*)d_in[1];
    const float* bf = (const float*)d_in[2];
    const float* Wg = (const float*)d_in[3];
    const float* bg = (const float*)d_in[4];
    const float* Wh = (const float*)d_in[5];
    const float* bh = (const float*)d_in[6];
    float* out = (float*)d_out;

    const int SMEM = 98304;  // 3 stages x (16KB A + 16KB B)
    cudaFuncSetAttribute(projfg_kernel,   cudaFuncAttributeMaxDynamicSharedMemorySize, SMEM);
    cudaFuncSetAttribute(projh_kernel,    cudaFuncAttributeMaxDynamicSharedMemorySize, SMEM);
    cudaFuncSetAttribute(energy_kernel,   cudaFuncAttributeMaxDynamicSharedMemorySize, SMEM);
    cudaFuncSetAttribute(residual_kernel, cudaFuncAttributeMaxDynamicSharedMemorySize, SMEM);

    const int NW = (HC_ + HC_ + C_) * C_;
    permute_w_kernel<<<(NW + 255) / 256, 256>>>(Wf, Wg, Wh);
    transpose_x_kernel<<<dim3(N_ / 32, C_ / 32, B_), dim3(32, 8)>>>(x);
    projfg_kernel<<<dim3(32, 4, B_), 256, SMEM>>>(bf, bg);
    projh_kernel<<<dim3(32, 4, B_), 256, SMEM>>>(bh);
    energy_kernel<<<dim3(32, 32, B_), 256, SMEM>>>();
    softmax_kernel<<<dim3(N_, B_), 256>>>();
    colmean_part_kernel<<<dim3(16, 32, B_), 256>>>();
    colmean_final_kernel<<<dim3(16, B_), 256>>>(out);
    residual_kernel<<<dim3(32, 4, B_), 256, SMEM>>>(out);
}

// round 9
// speedup vs baseline: 2.0028x; 1.2985x over previous
#include <cuda_runtime.h>
#include <math_constants.h>
#include <cstdint>

#define B_  4
#define C_  512
#define HC_ 256
#define N_  4096

// ---------------------------------------------------------------------------
// K-group permutation: within each 8-wide K group, position p holds
// k = (0,4,1,5,2,6,3,7)[p] so that fragment pairs (k, k+4) are adjacent.
// ---------------------------------------------------------------------------
__host__ __device__ __forceinline__ int perm8(int q)  { return ((q & 3) << 1) | (q >> 2); }
__device__ __forceinline__ int permpos(int c) { return (c & ~7) | perm8(c & 7); }

// ---------------------------------------------------------------------------
// Device scratch (all K-contraction dims stored permuted)
// ---------------------------------------------------------------------------
__device__ float g_xt[(size_t)B_ * N_ * C_];    // x^T: [b][n][c-perm]
__device__ float g_Wp[(size_t)(HC_ + HC_ + C_) * C_]; // Wf|Wg|Wh, [o][c-perm]
__device__ float g_ft[(size_t)B_ * N_ * HC_];   // f^T: [b][n][hc-perm]  (fp32)
__device__ float g_gt[(size_t)B_ * N_ * HC_];   // g^T: [b][n][hc-perm]  (tf32-rounded)
__device__ float g_h [(size_t)B_ * C_ * N_];    // h:   [b][c][n-perm]   (tf32-rounded)
__device__ float g_E [(size_t)B_ * N_ * N_];    // energy/corr [b][j][k-perm]
__device__ float g_part[(size_t)B_ * 32 * N_];  // colmean partials (positions)

// ---------------------------------------------------------------------------
// Helpers (baseline PTX only — ptxas targets sm_103, no 'a'-gated instrs)
// ---------------------------------------------------------------------------
__device__ __forceinline__ uint32_t su32(const void* p) {
    uint32_t a;
    asm("{ .reg .u64 t; cvta.to.shared.u64 t, %1; cvt.u32.u64 %0, t; }" : "=r"(a) : "l"(p));
    return a;
}
__device__ __forceinline__ void cp_async16(uint32_t dst, const void* src) {
    asm volatile("cp.async.cg.shared.global [%0], [%1], 16;" :: "r"(dst), "l"(src) : "memory");
}
__device__ __forceinline__ void cp_commit() {
    asm volatile("cp.async.commit_group;" ::: "memory");
}
__device__ __forceinline__ void cp_wait0() {
    asm volatile("cp.async.wait_group 0;" ::: "memory");
}
__device__ __forceinline__ void cp_wait1() {
    asm volatile("cp.async.wait_group 1;" ::: "memory");
}
__device__ __forceinline__ uint32_t f2tf(float f) {
    uint32_t r;
    asm("cvt.rna.tf32.f32 %0, %1;" : "=r"(r) : "f"(f));
    return r;
}
// Truncation-based split: hi = top tf32 bits (LOP3), lo = v - hi (exact).
__device__ __forceinline__ void split_m(float v, uint32_t& hi, uint32_t& lo) {
    hi = __float_as_uint(v) & 0xFFFFE000u;
    lo = __float_as_uint(v - __uint_as_float(hi));
}
__device__ __forceinline__ void mma_tf32(float* d, const uint32_t* a, const uint32_t* b) {
    asm volatile(
        "mma.sync.aligned.m16n8k8.row.col.f32.tf32.tf32.f32 "
        "{%0,%1,%2,%3}, {%4,%5,%6,%7}, {%8,%9}, {%0,%1,%2,%3};"
        : "+f"(d[0]), "+f"(d[1]), "+f"(d[2]), "+f"(d[3])
        : "r"(a[0]), "r"(a[1]), "r"(a[2]), "r"(a[3]), "r"(b[0]), "r"(b[1]));
}

// fast exp(t) for t <= 0: exp2 via degree-5 minimax poly on FMA pipe (no MUFU)
__device__ __forceinline__ float fast_exp_neg(float t) {
    float z = fmaxf(t * 1.4426950408889634f, -120.0f);
    float fi = floorf(z);
    float f = z - fi;
    float p =              0.00133335581f;
    p = fmaf(p, f,         0.00961812910f);
    p = fmaf(p, f,         0.0555041086f);
    p = fmaf(p, f,         0.240226462f);
    p = fmaf(p, f,         0.693147182f);
    p = fmaf(p, f,         1.0f);
    return p * __int_as_float(((int)fi + 127) << 23);
}

// smem float-index with XOR swizzle: row stride 32 floats (128B), 16B chunks
#define SWZ(r, k) (((r) * 32) + ((k) ^ (((r) & 7) * 4)))

extern __shared__ float dynsm_f[];

// ---------------------------------------------------------------------------
// GEMM core: D[128 x 128] += A[128 x K] @ B[128 x K]^T  (tf32 HMMA, fp32 acc)
// A, B K-contig with PERMUTED k-groups; fragment pairs load as LDS.64.
// PASSES = 3: split A and B (hi*hi, hi*lo, lo*hi)      — full 3xTF32
// PASSES = 2: split A only; B already exactly tf32     — a_hi*b, a_lo*b
// PASSES = 1: both operands exactly tf32               — single exact pass
// smem: 3 stages x (A 16KB + B 16KB) = 96KB.
// ---------------------------------------------------------------------------
template <int PASSES>
__device__ __forceinline__ void gemm_core(
    const float* __restrict__ A, int lda,
    const float* __restrict__ Bm, int ldb,
    int nK, float acc[4][4][4])
{
    float* sm = dynsm_f;
    const int tid  = threadIdx.x;
    const int lr   = tid >> 3;         // 0..31
    const int lc4  = (tid & 7) * 4;    // 0,4,...,28
    const int lane = tid & 31, warp = tid >> 5;
    const int wr = warp >> 2, wc = warp & 3;
    const int g = lane >> 2, tg = lane & 3;
    const int fchunk = tg >> 1;
    const int foff   = (tg & 1) << 1;

    auto issue = [&](int s, int kt) {
        const int k0 = kt * 32;
        float* sa = sm + s * 8192;
        float* sb = sa + 4096;
        #pragma unroll
        for (int p = 0; p < 4; ++p) {
            const int r = p * 32 + lr;
            cp_async16(su32(&sa[SWZ(r, lc4)]), &A [(size_t)r * lda + k0 + lc4]);
            cp_async16(su32(&sb[SWZ(r, lc4)]), &Bm[(size_t)r * ldb + k0 + lc4]);
        }
        cp_commit();
    };

    issue(0, 0);
    if (nK > 1) issue(1, 1);

    for (int kt = 0; kt < nK; ++kt) {
        const int s = kt % 3;
        if (kt + 1 < nK) cp_wait1(); else cp_wait0();
        __syncthreads();
        if (kt + 2 < nK) issue((kt + 2) % 3, kt + 2);

        const float* sa = sm + s * 8192;
        const float* sb = sa + 4096;
        #pragma unroll
        for (int k8 = 0; k8 < 4; ++k8) {
            const int chunk = (k8 << 1) | fchunk;
            uint32_t afh[4][4], afl[4][4], bfh[4][2], bfl[4][2];
            #pragma unroll
            for (int am = 0; am < 4; ++am) {
                const int r0 = wr * 64 + am * 16 + g;
                const int r1 = r0 + 8;
                float2 p0 = *reinterpret_cast<const float2*>(
                    &sa[r0 * 32 + ((chunk ^ (r0 & 7)) << 2) + foff]);
                float2 p1 = *reinterpret_cast<const float2*>(
                    &sa[r1 * 32 + ((chunk ^ (r1 & 7)) << 2) + foff]);
                if (PASSES >= 2) {
                    split_m(p0.x, afh[am][0], afl[am][0]);
                    split_m(p1.x, afh[am][1], afl[am][1]);
                    split_m(p0.y, afh[am][2], afl[am][2]);
                    split_m(p1.y, afh[am][3], afl[am][3]);
                } else {
                    afh[am][0] = __float_as_uint(p0.x);
                    afh[am][1] = __float_as_uint(p1.x);
                    afh[am][2] = __float_as_uint(p0.y);
                    afh[am][3] = __float_as_uint(p1.y);
                }
            }
            #pragma unroll
            for (int bn = 0; bn < 4; ++bn) {
                const int rb = wc * 32 + bn * 8 + g;
                float2 q = *reinterpret_cast<const float2*>(
                    &sb[rb * 32 + ((chunk ^ (rb & 7)) << 2) + foff]);
                if (PASSES == 3) {
                    split_m(q.x, bfh[bn][0], bfl[bn][0]);
                    split_m(q.y, bfh[bn][1], bfl[bn][1]);
                } else {
                    bfh[bn][0] = __float_as_uint(q.x);
                    bfh[bn][1] = __float_as_uint(q.y);
                }
            }
            // pass 1: a_hi * b_hi
            #pragma unroll
            for (int am = 0; am < 4; ++am)
                #pragma unroll
                for (int bn = 0; bn < 4; ++bn)
                    mma_tf32(acc[am][bn], afh[am], bfh[bn]);
            // pass 2 (PASSES==3): a_hi * b_lo
            if (PASSES == 3) {
                #pragma unroll
                for (int am = 0; am < 4; ++am)
                    #pragma unroll
                    for (int bn = 0; bn < 4; ++bn)
                        mma_tf32(acc[am][bn], afh[am], bfl[bn]);
            }
            // pass 3 (PASSES>=2): a_lo * b_hi
            if (PASSES >= 2) {
                #pragma unroll
                for (int am = 0; am < 4; ++am)
                    #pragma unroll
                    for (int bn = 0; bn < 4; ++bn)
                        mma_tf32(acc[am][bn], afl[am], bfh[bn]);
            }
        }
    }
}

// Epilogue (natural columns): Out[r][c] = acc. Used by residual.
__device__ __forceinline__ void epi_store(
    float acc[4][4][4], float* __restrict__ Out, int ld)
{
    const int lane = threadIdx.x & 31, warp = threadIdx.x >> 5;
    const int wr = warp >> 2, wc = warp & 3;
    const int g = lane >> 2, tg = lane & 3;
    #pragma unroll
    for (int am = 0; am < 4; ++am) {
        const int r = wr * 64 + am * 16 + g;
        #pragma unroll
        for (int bn = 0; bn < 4; ++bn) {
            const int c = wc * 32 + bn * 8 + tg * 2;
            float2 v0 = { acc[am][bn][0], acc[am][bn][1] };
            float2 v1 = { acc[am][bn][2], acc[am][bn][3] };
            *reinterpret_cast<float2*>(&Out[(size_t)r       * ld + c]) = v0;
            *reinterpret_cast<float2*>(&Out[(size_t)(r + 8) * ld + c]) = v1;
        }
    }
}

// Epilogue (permuted columns, optional tf32 rounding of the stored value).
__device__ __forceinline__ void epi_store_perm(
    float acc[4][4][4], float* __restrict__ Out, int ld,
    const float* __restrict__ bias_col, const float* __restrict__ bias_row,
    bool round_tf)
{
    const int lane = threadIdx.x & 31, warp = threadIdx.x >> 5;
    const int wr = warp >> 2, wc = warp & 3;
    const int g = lane >> 2, tg = lane & 3;
    #pragma unroll
    for (int am = 0; am < 4; ++am) {
        const int r = wr * 64 + am * 16 + g;
        const float br0 = bias_row ? bias_row[r]     : 0.f;
        const float br1 = bias_row ? bias_row[r + 8] : 0.f;
        #pragma unroll
        for (int bn = 0; bn < 4; ++bn) {
            const int c = wc * 32 + bn * 8 + tg * 2;
            const float b0 = bias_col ? bias_col[c]     : 0.f;
            const float b1 = bias_col ? bias_col[c + 1] : 0.f;
            float e0 = acc[am][bn][0] + b0 + br0;
            float e1 = acc[am][bn][1] + b1 + br0;
            float e2 = acc[am][bn][2] + b0 + br1;
            float e3 = acc[am][bn][3] + b1 + br1;
            if (round_tf) {
                e0 = __uint_as_float(f2tf(e0));
                e1 = __uint_as_float(f2tf(e1));
                e2 = __uint_as_float(f2tf(e2));
                e3 = __uint_as_float(f2tf(e3));
            }
            const int p0 = (c & ~7) | perm8(c & 7);
            const int p1 = (c & ~7) | perm8((c & 7) + 1);
            Out[(size_t)r       * ld + p0] = e0;
            Out[(size_t)r       * ld + p1] = e1;
            Out[(size_t)(r + 8) * ld + p0] = e2;
            Out[(size_t)(r + 8) * ld + p1] = e3;
        }
    }
}

// ---------------------------------------------------------------------------
// Producers
// ---------------------------------------------------------------------------
__global__ __launch_bounds__(256) void permute_w_kernel(
    const float* __restrict__ Wf, const float* __restrict__ Wg,
    const float* __restrict__ Wh)
{
    const int i = blockIdx.x * 256 + threadIdx.x;
    const int NW = (HC_ + HC_ + C_) * C_;
    if (i >= NW) return;
    float v;
    if (i < HC_ * C_)           v = Wf[i];
    else if (i < 2 * HC_ * C_)  v = Wg[i - HC_ * C_];
    else                        v = Wh[i - 2 * HC_ * C_];
    const int o = i / C_, c = i % C_;
    g_Wp[(size_t)o * C_ + permpos(c)] = v;
}

__global__ __launch_bounds__(256) void transpose_x_kernel(const float* __restrict__ x)
{
    __shared__ float t[32][33];
    const int b = blockIdx.z, n0 = blockIdx.x * 32, c0 = blockIdx.y * 32;
    const int tx = threadIdx.x, ty = threadIdx.y;
    const float* X = x + (size_t)b * C_ * N_;
    float* XT = g_xt + (size_t)b * N_ * C_;
    #pragma unroll
    for (int i = 0; i < 4; ++i)
        t[ty + i * 8][tx] = X[(size_t)(c0 + ty + i * 8) * N_ + n0 + tx];
    __syncthreads();
    const int cp = c0 + permpos(tx);
    #pragma unroll
    for (int i = 0; i < 4; ++i)
        XT[(size_t)(n0 + ty + i * 8) * C_ + cp] = t[tx][ty + i * 8];
}

// ---------------------------------------------------------------------------
// GEMM kernels
// ---------------------------------------------------------------------------
// f^T / g^T:  D[n][o] = xt[n][:] . W[o][:] -> [n][o-perm]
// ft kept fp32 (split in energy); gt ROUNDED to tf32 (exact B in energy).
__global__ __launch_bounds__(256, 2) void projfg_kernel(
    const float* __restrict__ bf, const float* __restrict__ bg)
{
    const int b = blockIdx.z, n0 = blockIdx.x * 128, ot = blockIdx.y;
    const float* A = g_xt + ((size_t)b * N_ + n0) * C_;
    const float* W; const float* bias; float* Out; int o0; bool rnd;
    if (ot < 2) { W = g_Wp + (size_t)(ot * 128) * C_;             bias = bf + ot * 128;       Out = g_ft + (size_t)b * N_ * HC_; o0 = ot * 128;       rnd = false; }
    else        { W = g_Wp + (size_t)(HC_ + (ot - 2) * 128) * C_; bias = bg + (ot - 2) * 128; Out = g_gt + (size_t)b * N_ * HC_; o0 = (ot - 2) * 128; rnd = true;  }

    float acc[4][4][4] = {};
    gemm_core<3>(A, C_, W, C_, C_ / 32, acc);
    epi_store_perm(acc, Out + (size_t)n0 * HC_ + o0, HC_, bias, nullptr, rnd);
}

// h:  D[c][n] = Wh[c][:] . xt[n][:] -> [c][n-perm], ROUNDED to tf32
// (residual then runs a single exact tf32 pass).
__global__ __launch_bounds__(256, 2) void projh_kernel(const float* __restrict__ bh)
{
    const int b = blockIdx.z, n0 = blockIdx.x * 128, c0 = blockIdx.y * 128;
    const float* A  = g_Wp + (size_t)(2 * HC_ + c0) * C_;
    const float* Bm = g_xt + ((size_t)b * N_ + n0) * C_;

    float acc[4][4][4] = {};
    gemm_core<3>(A, C_, Bm, C_, C_ / 32, acc);
    epi_store_perm(acc, g_h + (size_t)b * C_ * N_ + (size_t)c0 * N_ + n0, N_, nullptr, bh + c0, true);
}

// energy: D[j][k] = ft[j][:] . gt[k][:] -> [j][k-perm]
// ft fp32 (split), gt exactly tf32 -> 2-pass.
__global__ __launch_bounds__(256, 2) void energy_kernel()
{
    const int b = blockIdx.z, k0 = blockIdx.x * 128, j0 = blockIdx.y * 128;
    const float* A  = g_ft + ((size_t)b * N_ + j0) * HC_;
    const float* Bm = g_gt + ((size_t)b * N_ + k0) * HC_;

    float acc[4][4][4] = {};
    gemm_core<2>(A, HC_, Bm, HC_, HC_ / 32, acc);
    epi_store_perm(acc, g_E + (size_t)b * N_ * N_ + (size_t)j0 * N_ + k0, N_, nullptr, nullptr, false);
}

// residual: D[c][j] = h[c][:] . corr[j][:] — both exactly tf32 -> 1-pass.
__global__ __launch_bounds__(256, 2) void residual_kernel(float* __restrict__ out)
{
    const int b = blockIdx.z, j0 = blockIdx.x * 128, c0 = blockIdx.y * 128;
    const float* A  = g_h + (size_t)b * C_ * N_ + (size_t)c0 * N_;
    const float* Bm = g_E + (size_t)b * N_ * N_ + (size_t)j0 * N_;

    float acc[4][4][4] = {};
    gemm_core<1>(A, N_, Bm, N_, N_ / 32, acc);
    epi_store(acc, out + (size_t)b * C_ * N_ + (size_t)c0 * N_ + j0, N_);
}

// ---------------------------------------------------------------------------
// Softmax: elementwise over permuted row; writes corr rounded to tf32.
// ---------------------------------------------------------------------------
__global__ __launch_bounds__(256) void softmax_kernel()
{
    const int b = blockIdx.y;
    const int j = blockIdx.x;
    float* row = g_E + ((size_t)b * N_ + j) * N_;
    const int tid = threadIdx.x;

    float v[16];
    float m = -CUDART_INF_F;
    #pragma unroll
    for (int i = 0; i < 16; ++i) { v[i] = row[tid + i * 256]; m = fmaxf(m, v[i]); }

    __shared__ float red[8];
    #pragma unroll
    for (int o = 16; o; o >>= 1) m = fmaxf(m, __shfl_xor_sync(0xffffffffu, m, o));
    if ((tid & 31) == 0) red[tid >> 5] = m;
    __syncthreads();
    {
        float t = (tid < 8) ? red[tid] : -CUDART_INF_F;
        #pragma unroll
        for (int o = 4; o; o >>= 1) t = fmaxf(t, __shfl_xor_sync(0xffffffffu, t, o));
        if (tid == 0) red[0] = t;
    }
    __syncthreads();
    m = red[0];
    __syncthreads();

    float s = 0.f;
    #pragma unroll
    for (int i = 0; i < 16; ++i) { v[i] = fast_exp_neg(v[i] - m); s += v[i]; }
    #pragma unroll
    for (int o = 16; o; o >>= 1) s += __shfl_xor_sync(0xffffffffu, s, o);
    if ((tid & 31) == 0) red[tid >> 5] = s;
    __syncthreads();
    {
        float t = (tid < 8) ? red[tid] : 0.f;
        #pragma unroll
        for (int o = 4; o; o >>= 1) t += __shfl_xor_sync(0xffffffffu, t, o);
        if (tid == 0) red[0] = t;
    }
    __syncthreads();
    const float inv = 1.0f / red[0];

    #pragma unroll
    for (int i = 0; i < 16; ++i)
        row[tid + i * 256] = __uint_as_float(f2tf(v[i] * inv));
}

// ---------------------------------------------------------------------------
// Column mean (columns are permuted positions; final un-permutes the index)
// ---------------------------------------------------------------------------
__global__ __launch_bounds__(256) void colmean_part_kernel()
{
    const int b = blockIdx.z, jb = blockIdx.y;
    const int col = blockIdx.x * 256 + threadIdx.x;
    const float* E = g_E + (size_t)b * N_ * N_ + (size_t)jb * 128 * N_;
    float s = 0.f;
    #pragma unroll 8
    for (int j = 0; j < 128; ++j) s += E[(size_t)j * N_ + col];
    g_part[((size_t)b * 32 + jb) * N_ + col] = s;
}

__global__ __launch_bounds__(256) void colmean_final_kernel(float* __restrict__ out)
{
    const int b = blockIdx.y;
    const int col = blockIdx.x * 256 + threadIdx.x;  // permuted position
    float s = 0.f;
    #pragma unroll
    for (int p = 0; p < 32; ++p) s += g_part[((size_t)b * 32 + p) * N_ + col];
    const int m = (col & ~7) | ((col & 7) >> 1) | ((col & 1) << 2);  // iperm8
    out[(size_t)B_ * C_ * N_ + (size_t)b * N_ + m] = s * (1.0f / N_);
}

// ---------------------------------------------------------------------------
extern "C" void kernel_launch(void* const* d_in, const int* in_sizes, int n_in,
                              void* d_out, int out_size)
{
    const float* x  = (const float*)d_in[0];
    const float* Wf = (const float*)d_in[1];
    const float* bf = (const float*)d_in[2];
    const float* Wg = (const float*)d_in[3];
    const float* bg = (const float*)d_in[4];
    const float* Wh = (const float*)d_in[5];
    const float* bh = (const float*)d_in[6];
    float* out = (float*)d_out;

    const int SMEM = 98304;  // 3 stages x (16KB A + 16KB B)
    cudaFuncSetAttribute(projfg_kernel,   cudaFuncAttributeMaxDynamicSharedMemorySize, SMEM);
    cudaFuncSetAttribute(projh_kernel,    cudaFuncAttributeMaxDynamicSharedMemorySize, SMEM);
    cudaFuncSetAttribute(energy_kernel,   cudaFuncAttributeMaxDynamicSharedMemorySize, SMEM);
    cudaFuncSetAttribute(residual_kernel, cudaFuncAttributeMaxDynamicSharedMemorySize, SMEM);

    const int NW = (HC_ + HC_ + C_) * C_;
    permute_w_kernel<<<(NW + 255) / 256, 256>>>(Wf, Wg, Wh);
    transpose_x_kernel<<<dim3(N_ / 32, C_ / 32, B_), dim3(32, 8)>>>(x);
    projfg_kernel<<<dim3(32, 4, B_), 256, SMEM>>>(bf, bg);
    projh_kernel<<<dim3(32, 4, B_), 256, SMEM>>>(bh);
    energy_kernel<<<dim3(32, 32, B_), 256, SMEM>>>();
    softmax_kernel<<<dim3(N_, B_), 256>>>();
    colmean_part_kernel<<<dim3(16, 32, B_), 256>>>();
    colmean_final_kernel<<<dim3(16, B_), 256>>>(out);
    residual_kernel<<<dim3(32, 4, B_), 256, SMEM>>>(out);
}

// round 10
// speedup vs baseline: 2.0631x; 1.0301x over previous
#include <cuda_runtime.h>
#include <math_constants.h>
#include <cstdint>

#define B_  4
#define C_  512
#define HC_ 256
#define N_  4096

// ---------------------------------------------------------------------------
// K-group permutation: within each 8-wide K group, position p holds
// k = (0,4,1,5,2,6,3,7)[p] so that fragment pairs (k, k+4) are adjacent.
// ---------------------------------------------------------------------------
__host__ __device__ __forceinline__ int perm8(int q)  { return ((q & 3) << 1) | (q >> 2); }
__device__ __forceinline__ int permpos(int c) { return (c & ~7) | perm8(c & 7); }

// ---------------------------------------------------------------------------
// Device scratch (all K-contraction dims stored permuted)
// ---------------------------------------------------------------------------
__device__ float g_xt[(size_t)B_ * N_ * C_];    // x^T: [b][n][c-perm]
__device__ float g_Wp[(size_t)(HC_ + HC_ + C_) * C_]; // Wf|Wg|Wh, [o][c-perm]
__device__ float g_ft[(size_t)B_ * N_ * HC_];   // f^T: [b][n][hc-perm]  (fp32)
__device__ float g_gt[(size_t)B_ * N_ * HC_];   // g^T: [b][n][hc-perm]  (tf32-rounded)
__device__ float g_h [(size_t)B_ * C_ * N_];    // h:   [b][c][n-perm]   (tf32-rounded)
__device__ float g_E [(size_t)B_ * N_ * N_];    // energy/corr [b][j][k-perm]
__device__ float g_part[(size_t)B_ * 512 * N_]; // colmean partials (8 rows each)

// ---------------------------------------------------------------------------
// Helpers (baseline PTX only — ptxas targets sm_103, no 'a'-gated instrs)
// ---------------------------------------------------------------------------
__device__ __forceinline__ uint32_t su32(const void* p) {
    uint32_t a;
    asm("{ .reg .u64 t; cvta.to.shared.u64 t, %1; cvt.u32.u64 %0, t; }" : "=r"(a) : "l"(p));
    return a;
}
__device__ __forceinline__ void cp_async16(uint32_t dst, const void* src) {
    asm volatile("cp.async.cg.shared.global [%0], [%1], 16;" :: "r"(dst), "l"(src) : "memory");
}
__device__ __forceinline__ void cp_commit() {
    asm volatile("cp.async.commit_group;" ::: "memory");
}
__device__ __forceinline__ void cp_wait0() {
    asm volatile("cp.async.wait_group 0;" ::: "memory");
}
__device__ __forceinline__ void cp_wait1() {
    asm volatile("cp.async.wait_group 1;" ::: "memory");
}
__device__ __forceinline__ uint32_t f2tf(float f) {
    uint32_t r;
    asm("cvt.rna.tf32.f32 %0, %1;" : "=r"(r) : "f"(f));
    return r;
}
// Truncation-based split: hi = top tf32 bits (LOP3), lo = v - hi (exact).
__device__ __forceinline__ void split_m(float v, uint32_t& hi, uint32_t& lo) {
    hi = __float_as_uint(v) & 0xFFFFE000u;
    lo = __float_as_uint(v - __uint_as_float(hi));
}
__device__ __forceinline__ void mma_tf32(float* d, const uint32_t* a, const uint32_t* b) {
    asm volatile(
        "mma.sync.aligned.m16n8k8.row.col.f32.tf32.tf32.f32 "
        "{%0,%1,%2,%3}, {%4,%5,%6,%7}, {%8,%9}, {%0,%1,%2,%3};"
        : "+f"(d[0]), "+f"(d[1]), "+f"(d[2]), "+f"(d[3])
        : "r"(a[0]), "r"(a[1]), "r"(a[2]), "r"(a[3]), "r"(b[0]), "r"(b[1]));
}

// fast exp(t) for t <= 0: exp2 via degree-5 minimax poly on FMA pipe (no MUFU)
__device__ __forceinline__ float fast_exp_neg(float t) {
    float z = fmaxf(t * 1.4426950408889634f, -120.0f);
    float fi = floorf(z);
    float f = z - fi;
    float p =              0.00133335581f;
    p = fmaf(p, f,         0.00961812910f);
    p = fmaf(p, f,         0.0555041086f);
    p = fmaf(p, f,         0.240226462f);
    p = fmaf(p, f,         0.693147182f);
    p = fmaf(p, f,         1.0f);
    return p * __int_as_float(((int)fi + 127) << 23);
}

// smem float-index with XOR swizzle: row stride 32 floats (128B), 16B chunks
#define SWZ(r, k) (((r) * 32) + ((k) ^ (((r) & 7) * 4)))

extern __shared__ float dynsm_f[];

// ---------------------------------------------------------------------------
// GEMM core: D[128 x 128] += A[128 x K] @ B[128 x K]^T  (tf32 HMMA, fp32 acc)
// A, B K-contig with PERMUTED k-groups; fragment pairs load as LDS.64.
// PASSES = 3: split A and B (hi*hi, hi*lo, lo*hi)      — full 3xTF32
// PASSES = 2: split A only; B already exactly tf32     — a_hi*b, a_lo*b
// PASSES = 1: both operands exactly tf32               — single exact pass
// smem: 3 stages x (A 16KB + B 16KB) = 96KB.
// ---------------------------------------------------------------------------
template <int PASSES>
__device__ __forceinline__ void gemm_core(
    const float* __restrict__ A, int lda,
    const float* __restrict__ Bm, int ldb,
    int nK, float acc[4][4][4])
{
    float* sm = dynsm_f;
    const int tid  = threadIdx.x;
    const int lr   = tid >> 3;         // 0..31
    const int lc4  = (tid & 7) * 4;    // 0,4,...,28
    const int lane = tid & 31, warp = tid >> 5;
    const int wr = warp >> 2, wc = warp & 3;
    const int g = lane >> 2, tg = lane & 3;
    const int fchunk = tg >> 1;
    const int foff   = (tg & 1) << 1;

    auto issue = [&](int s, int kt) {
        const int k0 = kt * 32;
        float* sa = sm + s * 8192;
        float* sb = sa + 4096;
        #pragma unroll
        for (int p = 0; p < 4; ++p) {
            const int r = p * 32 + lr;
            cp_async16(su32(&sa[SWZ(r, lc4)]), &A [(size_t)r * lda + k0 + lc4]);
            cp_async16(su32(&sb[SWZ(r, lc4)]), &Bm[(size_t)r * ldb + k0 + lc4]);
        }
        cp_commit();
    };

    issue(0, 0);
    if (nK > 1) issue(1, 1);

    for (int kt = 0; kt < nK; ++kt) {
        const int s = kt % 3;
        if (kt + 1 < nK) cp_wait1(); else cp_wait0();
        __syncthreads();
        if (kt + 2 < nK) issue((kt + 2) % 3, kt + 2);

        const float* sa = sm + s * 8192;
        const float* sb = sa + 4096;
        #pragma unroll
        for (int k8 = 0; k8 < 4; ++k8) {
            const int chunk = (k8 << 1) | fchunk;
            uint32_t afh[4][4], afl[4][4], bfh[4][2], bfl[4][2];
            #pragma unroll
            for (int am = 0; am < 4; ++am) {
                const int r0 = wr * 64 + am * 16 + g;
                const int r1 = r0 + 8;
                float2 p0 = *reinterpret_cast<const float2*>(
                    &sa[r0 * 32 + ((chunk ^ (r0 & 7)) << 2) + foff]);
                float2 p1 = *reinterpret_cast<const float2*>(
                    &sa[r1 * 32 + ((chunk ^ (r1 & 7)) << 2) + foff]);
                if (PASSES >= 2) {
                    split_m(p0.x, afh[am][0], afl[am][0]);
                    split_m(p1.x, afh[am][1], afl[am][1]);
                    split_m(p0.y, afh[am][2], afl[am][2]);
                    split_m(p1.y, afh[am][3], afl[am][3]);
                } else {
                    afh[am][0] = __float_as_uint(p0.x);
                    afh[am][1] = __float_as_uint(p1.x);
                    afh[am][2] = __float_as_uint(p0.y);
                    afh[am][3] = __float_as_uint(p1.y);
                }
            }
            #pragma unroll
            for (int bn = 0; bn < 4; ++bn) {
                const int rb = wc * 32 + bn * 8 + g;
                float2 q = *reinterpret_cast<const float2*>(
                    &sb[rb * 32 + ((chunk ^ (rb & 7)) << 2) + foff]);
                if (PASSES == 3) {
                    split_m(q.x, bfh[bn][0], bfl[bn][0]);
                    split_m(q.y, bfh[bn][1], bfl[bn][1]);
                } else {
                    bfh[bn][0] = __float_as_uint(q.x);
                    bfh[bn][1] = __float_as_uint(q.y);
                }
            }
            #pragma unroll
            for (int am = 0; am < 4; ++am)
                #pragma unroll
                for (int bn = 0; bn < 4; ++bn)
                    mma_tf32(acc[am][bn], afh[am], bfh[bn]);
            if (PASSES == 3) {
                #pragma unroll
                for (int am = 0; am < 4; ++am)
                    #pragma unroll
                    for (int bn = 0; bn < 4; ++bn)
                        mma_tf32(acc[am][bn], afh[am], bfl[bn]);
            }
            if (PASSES >= 2) {
                #pragma unroll
                for (int am = 0; am < 4; ++am)
                    #pragma unroll
                    for (int bn = 0; bn < 4; ++bn)
                        mma_tf32(acc[am][bn], afl[am], bfh[bn]);
            }
        }
    }
}

// Epilogue (natural columns): Out[r][c] = acc. Used by residual.
__device__ __forceinline__ void epi_store(
    float acc[4][4][4], float* __restrict__ Out, int ld)
{
    const int lane = threadIdx.x & 31, warp = threadIdx.x >> 5;
    const int wr = warp >> 2, wc = warp & 3;
    const int g = lane >> 2, tg = lane & 3;
    #pragma unroll
    for (int am = 0; am < 4; ++am) {
        const int r = wr * 64 + am * 16 + g;
        #pragma unroll
        for (int bn = 0; bn < 4; ++bn) {
            const int c = wc * 32 + bn * 8 + tg * 2;
            float2 v0 = { acc[am][bn][0], acc[am][bn][1] };
            float2 v1 = { acc[am][bn][2], acc[am][bn][3] };
            *reinterpret_cast<float2*>(&Out[(size_t)r       * ld + c]) = v0;
            *reinterpret_cast<float2*>(&Out[(size_t)(r + 8) * ld + c]) = v1;
        }
    }
}

// Epilogue (permuted columns, optional tf32 rounding of the stored value).
__device__ __forceinline__ void epi_store_perm(
    float acc[4][4][4], float* __restrict__ Out, int ld,
    const float* __restrict__ bias_col, const float* __restrict__ bias_row,
    bool round_tf)
{
    const int lane = threadIdx.x & 31, warp = threadIdx.x >> 5;
    const int wr = warp >> 2, wc = warp & 3;
    const int g = lane >> 2, tg = lane & 3;
    #pragma unroll
    for (int am = 0; am < 4; ++am) {
        const int r = wr * 64 + am * 16 + g;
        const float br0 = bias_row ? bias_row[r]     : 0.f;
        const float br1 = bias_row ? bias_row[r + 8] : 0.f;
        #pragma unroll
        for (int bn = 0; bn < 4; ++bn) {
            const int c = wc * 32 + bn * 8 + tg * 2;
            const float b0 = bias_col ? bias_col[c]     : 0.f;
            const float b1 = bias_col ? bias_col[c + 1] : 0.f;
            float e0 = acc[am][bn][0] + b0 + br0;
            float e1 = acc[am][bn][1] + b1 + br0;
            float e2 = acc[am][bn][2] + b0 + br1;
            float e3 = acc[am][bn][3] + b1 + br1;
            if (round_tf) {
                e0 = __uint_as_float(f2tf(e0));
                e1 = __uint_as_float(f2tf(e1));
                e2 = __uint_as_float(f2tf(e2));
                e3 = __uint_as_float(f2tf(e3));
            }
            const int p0 = (c & ~7) | perm8(c & 7);
            const int p1 = (c & ~7) | perm8((c & 7) + 1);
            Out[(size_t)r       * ld + p0] = e0;
            Out[(size_t)r       * ld + p1] = e1;
            Out[(size_t)(r + 8) * ld + p0] = e2;
            Out[(size_t)(r + 8) * ld + p1] = e3;
        }
    }
}

// ---------------------------------------------------------------------------
// Producers
// ---------------------------------------------------------------------------
__global__ __launch_bounds__(256) void permute_w_kernel(
    const float* __restrict__ Wf, const float* __restrict__ Wg,
    const float* __restrict__ Wh)
{
    const int i = blockIdx.x * 256 + threadIdx.x;
    const int NW = (HC_ + HC_ + C_) * C_;
    if (i >= NW) return;
    float v;
    if (i < HC_ * C_)           v = Wf[i];
    else if (i < 2 * HC_ * C_)  v = Wg[i - HC_ * C_];
    else                        v = Wh[i - 2 * HC_ * C_];
    const int o = i / C_, c = i % C_;
    g_Wp[(size_t)o * C_ + permpos(c)] = v;
}

__global__ __launch_bounds__(256) void transpose_x_kernel(const float* __restrict__ x)
{
    __shared__ float t[32][33];
    const int b = blockIdx.z, n0 = blockIdx.x * 32, c0 = blockIdx.y * 32;
    const int tx = threadIdx.x, ty = threadIdx.y;
    const float* X = x + (size_t)b * C_ * N_;
    float* XT = g_xt + (size_t)b * N_ * C_;
    #pragma unroll
    for (int i = 0; i < 4; ++i)
        t[ty + i * 8][tx] = X[(size_t)(c0 + ty + i * 8) * N_ + n0 + tx];
    __syncthreads();
    const int cp = c0 + permpos(tx);
    #pragma unroll
    for (int i = 0; i < 4; ++i)
        XT[(size_t)(n0 + ty + i * 8) * C_ + cp] = t[tx][ty + i * 8];
}

// ---------------------------------------------------------------------------
// Merged projection kernel.
//   blockIdx.y 0..3 : f/g tiles  (D[n][o] = xt . W,  -> ft / gt, gt rounded)
//   blockIdx.y 4..7 : h tiles    (D[c][n] = Wh . xt, -> g_h, rounded)
// ---------------------------------------------------------------------------
__global__ __launch_bounds__(256, 2) void proj_kernel(
    const float* __restrict__ bf, const float* __restrict__ bg,
    const float* __restrict__ bh)
{
    const int b = blockIdx.z, n0 = blockIdx.x * 128, yt = blockIdx.y;
    float acc[4][4][4] = {};

    if (yt < 4) {
        const float* A = g_xt + ((size_t)b * N_ + n0) * C_;
        const float* W; const float* bias; float* Out; int o0; bool rnd;
        if (yt < 2) { W = g_Wp + (size_t)(yt * 128) * C_;             bias = bf + yt * 128;       Out = g_ft + (size_t)b * N_ * HC_; o0 = yt * 128;       rnd = false; }
        else        { W = g_Wp + (size_t)(HC_ + (yt - 2) * 128) * C_; bias = bg + (yt - 2) * 128; Out = g_gt + (size_t)b * N_ * HC_; o0 = (yt - 2) * 128; rnd = true;  }
        gemm_core<3>(A, C_, W, C_, C_ / 32, acc);
        epi_store_perm(acc, Out + (size_t)n0 * HC_ + o0, HC_, bias, nullptr, rnd);
    } else {
        const int c0 = (yt - 4) * 128;
        const float* A  = g_Wp + (size_t)(2 * HC_ + c0) * C_;
        const float* Bm = g_xt + ((size_t)b * N_ + n0) * C_;
        gemm_core<3>(A, C_, Bm, C_, C_ / 32, acc);
        epi_store_perm(acc, g_h + (size_t)b * C_ * N_ + (size_t)c0 * N_ + n0, N_, nullptr, bh + c0, true);
    }
}

// energy: D[j][k] = ft[j][:] . gt[k][:] -> [j][k-perm]; ft split, gt exact tf32.
__global__ __launch_bounds__(256, 2) void energy_kernel()
{
    const int b = blockIdx.z, k0 = blockIdx.x * 128, j0 = blockIdx.y * 128;
    const float* A  = g_ft + ((size_t)b * N_ + j0) * HC_;
    const float* Bm = g_gt + ((size_t)b * N_ + k0) * HC_;

    float acc[4][4][4] = {};
    gemm_core<2>(A, HC_, Bm, HC_, HC_ / 32, acc);
    epi_store_perm(acc, g_E + (size_t)b * N_ * N_ + (size_t)j0 * N_ + k0, N_, nullptr, nullptr, false);
}

// residual: D[c][j] = h[c][:] . corr[j][:] — both exactly tf32 -> 1-pass.
__global__ __launch_bounds__(256, 2) void residual_kernel(float* __restrict__ out)
{
    const int b = blockIdx.z, j0 = blockIdx.x * 128, c0 = blockIdx.y * 128;
    const float* A  = g_h + (size_t)b * C_ * N_ + (size_t)c0 * N_;
    const float* Bm = g_E + (size_t)b * N_ * N_ + (size_t)j0 * N_;

    float acc[4][4][4] = {};
    gemm_core<1>(A, N_, Bm, N_, N_ / 32, acc);
    epi_store(acc, out + (size_t)b * C_ * N_ + (size_t)c0 * N_ + j0, N_);
}

// ---------------------------------------------------------------------------
// Softmax over 8 rows per block; writes corr rounded to tf32 AND per-block
// column partial sums (fuses the old colmean_part 256MB re-read away).
// ---------------------------------------------------------------------------
__global__ __launch_bounds__(256) void softmax_kernel()
{
    const int b = blockIdx.y;
    const int j0 = blockIdx.x * 8;
    const int tid = threadIdx.x;
    __shared__ float red[8];

    float colacc[16];
    #pragma unroll
    for (int i = 0; i < 16; ++i) colacc[i] = 0.f;

    for (int r = 0; r < 8; ++r) {
        float* row = g_E + ((size_t)b * N_ + j0 + r) * N_;

        float v[16];
        float m = -CUDART_INF_F;
        #pragma unroll
        for (int i = 0; i < 16; ++i) { v[i] = row[tid + i * 256]; m = fmaxf(m, v[i]); }

        #pragma unroll
        for (int o = 16; o; o >>= 1) m = fmaxf(m, __shfl_xor_sync(0xffffffffu, m, o));
        if ((tid & 31) == 0) red[tid >> 5] = m;
        __syncthreads();
        {
            float t = (tid < 8) ? red[tid] : -CUDART_INF_F;
            #pragma unroll
            for (int o = 4; o; o >>= 1) t = fmaxf(t, __shfl_xor_sync(0xffffffffu, t, o));
            if (tid == 0) red[0] = t;
        }
        __syncthreads();
        m = red[0];
        __syncthreads();

        float s = 0.f;
        #pragma unroll
        for (int i = 0; i < 16; ++i) { v[i] = fast_exp_neg(v[i] - m); s += v[i]; }
        #pragma unroll
        for (int o = 16; o; o >>= 1) s += __shfl_xor_sync(0xffffffffu, s, o);
        if ((tid & 31) == 0) red[tid >> 5] = s;
        __syncthreads();
        {
            float t = (tid < 8) ? red[tid] : 0.f;
            #pragma unroll
            for (int o = 4; o; o >>= 1) t += __shfl_xor_sync(0xffffffffu, t, o);
            if (tid == 0) red[0] = t;
        }
        __syncthreads();
        const float inv = 1.0f / red[0];
        __syncthreads();

        #pragma unroll
        for (int i = 0; i < 16; ++i) {
            const float c = __uint_as_float(f2tf(v[i] * inv));
            row[tid + i * 256] = c;
            colacc[i] += c;
        }
    }

    float* part = g_part + ((size_t)b * 512 + blockIdx.x) * N_;
    #pragma unroll
    for (int i = 0; i < 16; ++i) part[tid + i * 256] = colacc[i];
}

// Column mean final: sum 512 partials per column; un-permute output index.
__global__ __launch_bounds__(256) void colmean_final_kernel(float* __restrict__ out)
{
    const int b = blockIdx.y;
    const int col = blockIdx.x * 256 + threadIdx.x;  // permuted position
    const float* part = g_part + (size_t)b * 512 * N_;
    float s = 0.f;
    #pragma unroll 8
    for (int p = 0; p < 512; ++p) s += part[(size_t)p * N_ + col];
    const int m = (col & ~7) | ((col & 7) >> 1) | ((col & 1) << 2);  // iperm8
    out[(size_t)B_ * C_ * N_ + (size_t)b * N_ + m] = s * (1.0f / N_);
}

// ---------------------------------------------------------------------------
extern "C" void kernel_launch(void* const* d_in, const int* in_sizes, int n_in,
                              void* d_out, int out_size)
{
    const float* x  = (const float*)d_in[0];
    const float* Wf = (const float*)d_in[1];
    const float* bf = (const float*)d_in[2];
    const float* Wg = (const float*)d_in[3];
    const float* bg = (const float*)d_in[4];
    const float* Wh = (const float*)d_in[5];
    const float* bh = (const float*)d_in[6];
    float* out = (float*)d_out;

    const int SMEM = 98304;  // 3 stages x (16KB A + 16KB B)
    cudaFuncSetAttribute(proj_kernel,     cudaFuncAttributeMaxDynamicSharedMemorySize, SMEM);
    cudaFuncSetAttribute(energy_kernel,   cudaFuncAttributeMaxDynamicSharedMemorySize, SMEM);
    cudaFuncSetAttribute(residual_kernel, cudaFuncAttributeMaxDynamicSharedMemorySize, SMEM);

    const int NW = (HC_ + HC_ + C_) * C_;
    permute_w_kernel<<<(NW + 255) / 256, 256>>>(Wf, Wg, Wh);
    transpose_x_kernel<<<dim3(N_ / 32, C_ / 32, B_), dim3(32, 8)>>>(x);
    proj_kernel<<<dim3(32, 8, B_), 256, SMEM>>>(bf, bg, bh);
    energy_kernel<<<dim3(32, 32, B_), 256, SMEM>>>();
    softmax_kernel<<<dim3(512, B_), 256>>>();
    colmean_final_kernel<<<dim3(16, B_), 256>>>(out);
    residual_kernel<<<dim3(32, 4, B_), 256, SMEM>>>(out);
}

// round 11
// speedup vs baseline: 2.0663x; 1.0015x over previous
#include <cuda_runtime.h>
#include <math_constants.h>
#include <cstdint>

#define B_  4
#define C_  512
#define HC_ 256
#define N_  4096

// ---------------------------------------------------------------------------
// K-group permutation: within each 8-wide K group, position p holds
// k = (0,4,1,5,2,6,3,7)[p] so that fragment pairs (k, k+4) are adjacent.
// ---------------------------------------------------------------------------
__host__ __device__ __forceinline__ int perm8(int q)  { return ((q & 3) << 1) | (q >> 2); }
__device__ __forceinline__ int permpos(int c) { return (c & ~7) | perm8(c & 7); }

// ---------------------------------------------------------------------------
// Device scratch (all K-contraction dims stored permuted)
// ---------------------------------------------------------------------------
__device__ float g_xt[(size_t)B_ * N_ * C_];    // x^T: [b][n][c-perm]
__device__ float g_Wp[(size_t)(HC_ + HC_ + C_) * C_]; // Wf|Wg|Wh, [o][c-perm]
__device__ float g_ft[(size_t)B_ * N_ * HC_];   // f^T: [b][n][hc-perm]  (fp32)
__device__ float g_gt[(size_t)B_ * N_ * HC_];   // g^T: [b][n][hc-perm]  (tf32-rounded)
__device__ float g_h [(size_t)B_ * C_ * N_];    // h:   [b][c][n-perm]   (tf32-rounded)
__device__ float g_E [(size_t)B_ * N_ * N_];    // energy/corr [b][j][k-perm]
__device__ float g_part[(size_t)B_ * 512 * N_]; // colmean partials (8 rows each)

// ---------------------------------------------------------------------------
// Helpers (baseline PTX only — ptxas targets sm_103, no 'a'-gated instrs)
// ---------------------------------------------------------------------------
__device__ __forceinline__ uint32_t su32(const void* p) {
    uint32_t a;
    asm("{ .reg .u64 t; cvta.to.shared.u64 t, %1; cvt.u32.u64 %0, t; }" : "=r"(a) : "l"(p));
    return a;
}
__device__ __forceinline__ void cp_async16(uint32_t dst, const void* src) {
    asm volatile("cp.async.cg.shared.global [%0], [%1], 16;" :: "r"(dst), "l"(src) : "memory");
}
__device__ __forceinline__ void cp_commit() {
    asm volatile("cp.async.commit_group;" ::: "memory");
}
__device__ __forceinline__ void cp_wait0() {
    asm volatile("cp.async.wait_group 0;" ::: "memory");
}
__device__ __forceinline__ void cp_wait1() {
    asm volatile("cp.async.wait_group 1;" ::: "memory");
}
__device__ __forceinline__ uint32_t f2tf(float f) {
    uint32_t r;
    asm("cvt.rna.tf32.f32 %0, %1;" : "=r"(r) : "f"(f));
    return r;
}
// Truncation-based split: hi = top tf32 bits (LOP3), lo = v - hi (exact).
__device__ __forceinline__ void split_m(float v, uint32_t& hi, uint32_t& lo) {
    hi = __float_as_uint(v) & 0xFFFFE000u;
    lo = __float_as_uint(v - __uint_as_float(hi));
}
__device__ __forceinline__ void mma_tf32(float* d, const uint32_t* a, const uint32_t* b) {
    asm volatile(
        "mma.sync.aligned.m16n8k8.row.col.f32.tf32.tf32.f32 "
        "{%0,%1,%2,%3}, {%4,%5,%6,%7}, {%8,%9}, {%0,%1,%2,%3};"
        : "+f"(d[0]), "+f"(d[1]), "+f"(d[2]), "+f"(d[3])
        : "r"(a[0]), "r"(a[1]), "r"(a[2]), "r"(a[3]), "r"(b[0]), "r"(b[1]));
}

// fast exp(t) for t <= 0: exp2 via degree-5 minimax poly on FMA pipe (no MUFU)
__device__ __forceinline__ float fast_exp_neg(float t) {
    float z = fmaxf(t * 1.4426950408889634f, -120.0f);
    float fi = floorf(z);
    float f = z - fi;
    float p =              0.00133335581f;
    p = fmaf(p, f,         0.00961812910f);
    p = fmaf(p, f,         0.0555041086f);
    p = fmaf(p, f,         0.240226462f);
    p = fmaf(p, f,         0.693147182f);
    p = fmaf(p, f,         1.0f);
    return p * __int_as_float(((int)fi + 127) << 23);
}

// smem float-index with XOR swizzle: row stride 32 floats (128B), 16B chunks
#define SWZ(r, k) (((r) * 32) + ((k) ^ (((r) & 7) * 4)))

extern __shared__ float dynsm_f[];

// ---------------------------------------------------------------------------
// GEMM core: D[128 x 128] += A[128 x K] @ B[128 x K]^T  (tf32 HMMA, fp32 acc)
// A, B K-contig with PERMUTED k-groups; fragment pairs load as LDS.64.
// PASSES = 3: split A and B (hi*hi, hi*lo, lo*hi)      — full 3xTF32
// PASSES = 2: split A only; B already exactly tf32     — a_hi*b, a_lo*b
// PASSES = 1: both operands exactly tf32               — single exact pass
// smem: 3 stages x (A 16KB + B 16KB) = 96KB.
// ---------------------------------------------------------------------------
template <int PASSES>
__device__ __forceinline__ void gemm_core(
    const float* __restrict__ A, int lda,
    const float* __restrict__ Bm, int ldb,
    int nK, float acc[4][4][4])
{
    float* sm = dynsm_f;
    const int tid  = threadIdx.x;
    const int lr   = tid >> 3;         // 0..31
    const int lc4  = (tid & 7) * 4;    // 0,4,...,28
    const int lane = tid & 31, warp = tid >> 5;
    const int wr = warp >> 2, wc = warp & 3;
    const int g = lane >> 2, tg = lane & 3;
    const int fchunk = tg >> 1;
    const int foff   = (tg & 1) << 1;

    auto issue = [&](int s, int kt) {
        const int k0 = kt * 32;
        float* sa = sm + s * 8192;
        float* sb = sa + 4096;
        #pragma unroll
        for (int p = 0; p < 4; ++p) {
            const int r = p * 32 + lr;
            cp_async16(su32(&sa[SWZ(r, lc4)]), &A [(size_t)r * lda + k0 + lc4]);
            cp_async16(su32(&sb[SWZ(r, lc4)]), &Bm[(size_t)r * ldb + k0 + lc4]);
        }
        cp_commit();
    };

    issue(0, 0);
    if (nK > 1) issue(1, 1);

    for (int kt = 0; kt < nK; ++kt) {
        const int s = kt % 3;
        if (kt + 1 < nK) cp_wait1(); else cp_wait0();
        __syncthreads();
        if (kt + 2 < nK) issue((kt + 2) % 3, kt + 2);

        const float* sa = sm + s * 8192;
        const float* sb = sa + 4096;
        #pragma unroll
        for (int k8 = 0; k8 < 4; ++k8) {
            const int chunk = (k8 << 1) | fchunk;
            uint32_t afh[4][4], afl[4][4], bfh[4][2], bfl[4][2];
            #pragma unroll
            for (int am = 0; am < 4; ++am) {
                const int r0 = wr * 64 + am * 16 + g;
                const int r1 = r0 + 8;
                float2 p0 = *reinterpret_cast<const float2*>(
                    &sa[r0 * 32 + ((chunk ^ (r0 & 7)) << 2) + foff]);
                float2 p1 = *reinterpret_cast<const float2*>(
                    &sa[r1 * 32 + ((chunk ^ (r1 & 7)) << 2) + foff]);
                if (PASSES >= 2) {
                    split_m(p0.x, afh[am][0], afl[am][0]);
                    split_m(p1.x, afh[am][1], afl[am][1]);
                    split_m(p0.y, afh[am][2], afl[am][2]);
                    split_m(p1.y, afh[am][3], afl[am][3]);
                } else {
                    afh[am][0] = __float_as_uint(p0.x);
                    afh[am][1] = __float_as_uint(p1.x);
                    afh[am][2] = __float_as_uint(p0.y);
                    afh[am][3] = __float_as_uint(p1.y);
                }
            }
            #pragma unroll
            for (int bn = 0; bn < 4; ++bn) {
                const int rb = wc * 32 + bn * 8 + g;
                float2 q = *reinterpret_cast<const float2*>(
                    &sb[rb * 32 + ((chunk ^ (rb & 7)) << 2) + foff]);
                if (PASSES == 3) {
                    split_m(q.x, bfh[bn][0], bfl[bn][0]);
                    split_m(q.y, bfh[bn][1], bfl[bn][1]);
                } else {
                    bfh[bn][0] = __float_as_uint(q.x);
                    bfh[bn][1] = __float_as_uint(q.y);
                }
            }
            #pragma unroll
            for (int am = 0; am < 4; ++am)
                #pragma unroll
                for (int bn = 0; bn < 4; ++bn)
                    mma_tf32(acc[am][bn], afh[am], bfh[bn]);
            if (PASSES == 3) {
                #pragma unroll
                for (int am = 0; am < 4; ++am)
                    #pragma unroll
                    for (int bn = 0; bn < 4; ++bn)
                        mma_tf32(acc[am][bn], afh[am], bfl[bn]);
            }
            if (PASSES >= 2) {
                #pragma unroll
                for (int am = 0; am < 4; ++am)
                    #pragma unroll
                    for (int bn = 0; bn < 4; ++bn)
                        mma_tf32(acc[am][bn], afl[am], bfh[bn]);
            }
        }
    }
}

// Epilogue (natural columns): Out[r][c] = acc. Used by residual.
__device__ __forceinline__ void epi_store(
    float acc[4][4][4], float* __restrict__ Out, int ld)
{
    const int lane = threadIdx.x & 31, warp = threadIdx.x >> 5;
    const int wr = warp >> 2, wc = warp & 3;
    const int g = lane >> 2, tg = lane & 3;
    #pragma unroll
    for (int am = 0; am < 4; ++am) {
        const int r = wr * 64 + am * 16 + g;
        #pragma unroll
        for (int bn = 0; bn < 4; ++bn) {
            const int c = wc * 32 + bn * 8 + tg * 2;
            float2 v0 = { acc[am][bn][0], acc[am][bn][1] };
            float2 v1 = { acc[am][bn][2], acc[am][bn][3] };
            *reinterpret_cast<float2*>(&Out[(size_t)r       * ld + c]) = v0;
            *reinterpret_cast<float2*>(&Out[(size_t)(r + 8) * ld + c]) = v1;
        }
    }
}

// Epilogue (permuted columns, optional tf32 rounding of the stored value).
__device__ __forceinline__ void epi_store_perm(
    float acc[4][4][4], float* __restrict__ Out, int ld,
    const float* __restrict__ bias_col, const float* __restrict__ bias_row,
    bool round_tf)
{
    const int lane = threadIdx.x & 31, warp = threadIdx.x >> 5;
    const int wr = warp >> 2, wc = warp & 3;
    const int g = lane >> 2, tg = lane & 3;
    #pragma unroll
    for (int am = 0; am < 4; ++am) {
        const int r = wr * 64 + am * 16 + g;
        const float br0 = bias_row ? bias_row[r]     : 0.f;
        const float br1 = bias_row ? bias_row[r + 8] : 0.f;
        #pragma unroll
        for (int bn = 0; bn < 4; ++bn) {
            const int c = wc * 32 + bn * 8 + tg * 2;
            const float b0 = bias_col ? bias_col[c]     : 0.f;
            const float b1 = bias_col ? bias_col[c + 1] : 0.f;
            float e0 = acc[am][bn][0] + b0 + br0;
            float e1 = acc[am][bn][1] + b1 + br0;
            float e2 = acc[am][bn][2] + b0 + br1;
            float e3 = acc[am][bn][3] + b1 + br1;
            if (round_tf) {
                e0 = __uint_as_float(f2tf(e0));
                e1 = __uint_as_float(f2tf(e1));
                e2 = __uint_as_float(f2tf(e2));
                e3 = __uint_as_float(f2tf(e3));
            }
            const int p0 = (c & ~7) | perm8(c & 7);
            const int p1 = (c & ~7) | perm8((c & 7) + 1);
            Out[(size_t)r       * ld + p0] = e0;
            Out[(size_t)r       * ld + p1] = e1;
            Out[(size_t)(r + 8) * ld + p0] = e2;
            Out[(size_t)(r + 8) * ld + p1] = e3;
        }
    }
}

// ---------------------------------------------------------------------------
// Producers
// ---------------------------------------------------------------------------
__global__ __launch_bounds__(256) void permute_w_kernel(
    const float* __restrict__ Wf, const float* __restrict__ Wg,
    const float* __restrict__ Wh)
{
    const int i = blockIdx.x * 256 + threadIdx.x;
    const int NW = (HC_ + HC_ + C_) * C_;
    if (i >= NW) return;
    float v;
    if (i < HC_ * C_)           v = Wf[i];
    else if (i < 2 * HC_ * C_)  v = Wg[i - HC_ * C_];
    else                        v = Wh[i - 2 * HC_ * C_];
    const int o = i / C_, c = i % C_;
    g_Wp[(size_t)o * C_ + permpos(c)] = v;
}

__global__ __launch_bounds__(256) void transpose_x_kernel(const float* __restrict__ x)
{
    __shared__ float t[32][33];
    const int b = blockIdx.z, n0 = blockIdx.x * 32, c0 = blockIdx.y * 32;
    const int tx = threadIdx.x, ty = threadIdx.y;
    const float* X = x + (size_t)b * C_ * N_;
    float* XT = g_xt + (size_t)b * N_ * C_;
    #pragma unroll
    for (int i = 0; i < 4; ++i)
        t[ty + i * 8][tx] = X[(size_t)(c0 + ty + i * 8) * N_ + n0 + tx];
    __syncthreads();
    const int cp = c0 + permpos(tx);
    #pragma unroll
    for (int i = 0; i < 4; ++i)
        XT[(size_t)(n0 + ty + i * 8) * C_ + cp] = t[tx][ty + i * 8];
}

// ---------------------------------------------------------------------------
// Merged projection kernel.
//   blockIdx.y 0..3 : f/g tiles  (D[n][o] = xt . W,  -> ft / gt, gt rounded)
//   blockIdx.y 4..7 : h tiles    (D[c][n] = Wh . xt, -> g_h, rounded)
// ---------------------------------------------------------------------------
__global__ __launch_bounds__(256, 2) void proj_kernel(
    const float* __restrict__ bf, const float* __restrict__ bg,
    const float* __restrict__ bh)
{
    const int b = blockIdx.z, n0 = blockIdx.x * 128, yt = blockIdx.y;
    float acc[4][4][4] = {};

    if (yt < 4) {
        const float* A = g_xt + ((size_t)b * N_ + n0) * C_;
        const float* W; const float* bias; float* Out; int o0; bool rnd;
        if (yt < 2) { W = g_Wp + (size_t)(yt * 128) * C_;             bias = bf + yt * 128;       Out = g_ft + (size_t)b * N_ * HC_; o0 = yt * 128;       rnd = false; }
        else        { W = g_Wp + (size_t)(HC_ + (yt - 2) * 128) * C_; bias = bg + (yt - 2) * 128; Out = g_gt + (size_t)b * N_ * HC_; o0 = (yt - 2) * 128; rnd = true;  }
        gemm_core<3>(A, C_, W, C_, C_ / 32, acc);
        epi_store_perm(acc, Out + (size_t)n0 * HC_ + o0, HC_, bias, nullptr, rnd);
    } else {
        const int c0 = (yt - 4) * 128;
        const float* A  = g_Wp + (size_t)(2 * HC_ + c0) * C_;
        const float* Bm = g_xt + ((size_t)b * N_ + n0) * C_;
        gemm_core<3>(A, C_, Bm, C_, C_ / 32, acc);
        epi_store_perm(acc, g_h + (size_t)b * C_ * N_ + (size_t)c0 * N_ + n0, N_, nullptr, bh + c0, true);
    }
}

// energy: D[j][k] = ft[j][:] . gt[k][:] -> [j][k-perm]; ft split, gt exact tf32.
__global__ __launch_bounds__(256, 2) void energy_kernel()
{
    const int b = blockIdx.z, k0 = blockIdx.x * 128, j0 = blockIdx.y * 128;
    const float* A  = g_ft + ((size_t)b * N_ + j0) * HC_;
    const float* Bm = g_gt + ((size_t)b * N_ + k0) * HC_;

    float acc[4][4][4] = {};
    gemm_core<2>(A, HC_, Bm, HC_, HC_ / 32, acc);
    epi_store_perm(acc, g_E + (size_t)b * N_ * N_ + (size_t)j0 * N_ + k0, N_, nullptr, nullptr, false);
}

// residual: D[c][j] = h[c][:] . corr[j][:] — both exactly tf32 -> 1-pass.
// Grid: x = c-tile (innermost, 4) so the 4 CTAs sharing each corr j0-tile are
// co-scheduled -> corr streamed from DRAM once, served from L2 to all 4.
__global__ __launch_bounds__(256, 2) void residual_kernel(float* __restrict__ out)
{
    const int b = blockIdx.z, c0 = blockIdx.x * 128, j0 = blockIdx.y * 128;
    const float* A  = g_h + (size_t)b * C_ * N_ + (size_t)c0 * N_;
    const float* Bm = g_E + (size_t)b * N_ * N_ + (size_t)j0 * N_;

    float acc[4][4][4] = {};
    gemm_core<1>(A, N_, Bm, N_, N_ / 32, acc);
    epi_store(acc, out + (size_t)b * C_ * N_ + (size_t)c0 * N_ + j0, N_);
}

// ---------------------------------------------------------------------------
// Softmax over 8 rows per block; writes corr rounded to tf32 AND per-block
// column partial sums (colmean fused).
// ---------------------------------------------------------------------------
__global__ __launch_bounds__(256) void softmax_kernel()
{
    const int b = blockIdx.y;
    const int j0 = blockIdx.x * 8;
    const int tid = threadIdx.x;
    __shared__ float red[8];

    float colacc[16];
    #pragma unroll
    for (int i = 0; i < 16; ++i) colacc[i] = 0.f;

    for (int r = 0; r < 8; ++r) {
        float* row = g_E + ((size_t)b * N_ + j0 + r) * N_;

        float v[16];
        float m = -CUDART_INF_F;
        #pragma unroll
        for (int i = 0; i < 16; ++i) { v[i] = row[tid + i * 256]; m = fmaxf(m, v[i]); }

        #pragma unroll
        for (int o = 16; o; o >>= 1) m = fmaxf(m, __shfl_xor_sync(0xffffffffu, m, o));
        if ((tid & 31) == 0) red[tid >> 5] = m;
        __syncthreads();
        {
            float t = (tid < 8) ? red[tid] : -CUDART_INF_F;
            #pragma unroll
            for (int o = 4; o; o >>= 1) t = fmaxf(t, __shfl_xor_sync(0xffffffffu, t, o));
            if (tid == 0) red[0] = t;
        }
        __syncthreads();
        m = red[0];
        __syncthreads();

        float s = 0.f;
        #pragma unroll
        for (int i = 0; i < 16; ++i) { v[i] = fast_exp_neg(v[i] - m); s += v[i]; }
        #pragma unroll
        for (int o = 16; o; o >>= 1) s += __shfl_xor_sync(0xffffffffu, s, o);
        if ((tid & 31) == 0) red[tid >> 5] = s;
        __syncthreads();
        {
            float t = (tid < 8) ? red[tid] : 0.f;
            #pragma unroll
            for (int o = 4; o; o >>= 1) t += __shfl_xor_sync(0xffffffffu, t, o);
            if (tid == 0) red[0] = t;
        }
        __syncthreads();
        const float inv = 1.0f / red[0];
        __syncthreads();

        #pragma unroll
        for (int i = 0; i < 16; ++i) {
            const float c = __uint_as_float(f2tf(v[i] * inv));
            row[tid + i * 256] = c;
            colacc[i] += c;
        }
    }

    float* part = g_part + ((size_t)b * 512 + blockIdx.x) * N_;
    #pragma unroll
    for (int i = 0; i < 16; ++i) part[tid + i * 256] = colacc[i];
}

// Column mean final: sum 512 partials per column; un-permute output index.
__global__ __launch_bounds__(256) void colmean_final_kernel(float* __restrict__ out)
{
    const int b = blockIdx.y;
    const int col = blockIdx.x * 256 + threadIdx.x;  // permuted position
    const float* part = g_part + (size_t)b * 512 * N_;
    float s = 0.f;
    #pragma unroll 8
    for (int p = 0; p < 512; ++p) s += part[(size_t)p * N_ + col];
    const int m = (col & ~7) | ((col & 7) >> 1) | ((col & 1) << 2);  // iperm8
    out[(size_t)B_ * C_ * N_ + (size_t)b * N_ + m] = s * (1.0f / N_);
}

// ---------------------------------------------------------------------------
extern "C" void kernel_launch(void* const* d_in, const int* in_sizes, int n_in,
                              void* d_out, int out_size)
{
    const float* x  = (const float*)d_in[0];
    const float* Wf = (const float*)d_in[1];
    const float* bf = (const float*)d_in[2];
    const float* Wg = (const float*)d_in[3];
    const float* bg = (const float*)d_in[4];
    const float* Wh = (const float*)d_in[5];
    const float* bh = (const float*)d_in[6];
    float* out = (float*)d_out;

    const int SMEM = 98304;  // 3 stages x (16KB A + 16KB B)
    cudaFuncSetAttribute(proj_kernel,     cudaFuncAttributeMaxDynamicSharedMemorySize, SMEM);
    cudaFuncSetAttribute(energy_kernel,   cudaFuncAttributeMaxDynamicSharedMemorySize, SMEM);
    cudaFuncSetAttribute(residual_kernel, cudaFuncAttributeMaxDynamicSharedMemorySize, SMEM);

    const int NW = (HC_ + HC_ + C_) * C_;
    permute_w_kernel<<<(NW + 255) / 256, 256>>>(Wf, Wg, Wh);
    transpose_x_kernel<<<dim3(N_ / 32, C_ / 32, B_), dim3(32, 8)>>>(x);
    proj_kernel<<<dim3(32, 8, B_), 256, SMEM>>>(bf, bg, bh);
    energy_kernel<<<dim3(32, 32, B_), 256, SMEM>>>();
    softmax_kernel<<<dim3(512, B_), 256>>>();
    colmean_final_kernel<<<dim3(16, B_), 256>>>(out);
    residual_kernel<<<dim3(4, 32, B_), 256, SMEM>>>(out);
}

// round 12
// speedup vs baseline: 2.0969x; 1.0148x over previous
#include <cuda_runtime.h>
#include <math_constants.h>
#include <cstdint>

#define B_  4
#define C_  512
#define HC_ 256
#define N_  4096

// ---------------------------------------------------------------------------
// K-group permutation: within each 8-wide K group, position p holds
// k = (0,4,1,5,2,6,3,7)[p] so that fragment pairs (k, k+4) are adjacent.
// ---------------------------------------------------------------------------
__host__ __device__ __forceinline__ int perm8(int q)  { return ((q & 3) << 1) | (q >> 2); }
__device__ __forceinline__ int permpos(int c) { return (c & ~7) | perm8(c & 7); }

// ---------------------------------------------------------------------------
// Device scratch (all K-contraction dims stored permuted)
// ---------------------------------------------------------------------------
__device__ float g_xt[(size_t)B_ * N_ * C_];    // x^T: [b][n][c-perm]
__device__ float g_Wp[(size_t)(HC_ + HC_ + C_) * C_]; // Wf|Wg|Wh, [o][c-perm]
__device__ float g_ft[(size_t)B_ * N_ * HC_];   // f^T: [b][n][hc-perm]  (fp32)
__device__ float g_gt[(size_t)B_ * N_ * HC_];   // g^T: [b][n][hc-perm]  (tf32-rounded)
__device__ float g_h [(size_t)B_ * C_ * N_];    // h:   [b][c][n-perm]   (tf32-rounded)
__device__ float g_E [(size_t)B_ * N_ * N_];    // energy/corr [b][j][k-perm]
__device__ float g_part[(size_t)B_ * 512 * N_]; // colmean partials (8 rows each)

// ---------------------------------------------------------------------------
// Helpers (baseline PTX only — ptxas targets sm_103, no 'a'-gated instrs)
// ---------------------------------------------------------------------------
__device__ __forceinline__ uint32_t su32(const void* p) {
    uint32_t a;
    asm("{ .reg .u64 t; cvta.to.shared.u64 t, %1; cvt.u32.u64 %0, t; }" : "=r"(a) : "l"(p));
    return a;
}
__device__ __forceinline__ void cp_async16(uint32_t dst, const void* src) {
    asm volatile("cp.async.cg.shared.global [%0], [%1], 16;" :: "r"(dst), "l"(src) : "memory");
}
__device__ __forceinline__ void cp_commit() {
    asm volatile("cp.async.commit_group;" ::: "memory");
}
__device__ __forceinline__ void cp_wait0() {
    asm volatile("cp.async.wait_group 0;" ::: "memory");
}
__device__ __forceinline__ void cp_wait1() {
    asm volatile("cp.async.wait_group 1;" ::: "memory");
}
__device__ __forceinline__ uint32_t f2tf(float f) {
    uint32_t r;
    asm("cvt.rna.tf32.f32 %0, %1;" : "=r"(r) : "f"(f));
    return r;
}
// Truncation-based split: hi = top tf32 bits (LOP3), lo = v - hi (exact).
__device__ __forceinline__ void split_m(float v, uint32_t& hi, uint32_t& lo) {
    hi = __float_as_uint(v) & 0xFFFFE000u;
    lo = __float_as_uint(v - __uint_as_float(hi));
}
__device__ __forceinline__ void mma_tf32(float* d, const uint32_t* a, const uint32_t* b) {
    asm volatile(
        "mma.sync.aligned.m16n8k8.row.col.f32.tf32.tf32.f32 "
        "{%0,%1,%2,%3}, {%4,%5,%6,%7}, {%8,%9}, {%0,%1,%2,%3};"
        : "+f"(d[0]), "+f"(d[1]), "+f"(d[2]), "+f"(d[3])
        : "r"(a[0]), "r"(a[1]), "r"(a[2]), "r"(a[3]), "r"(b[0]), "r"(b[1]));
}

// fast exp(t) for t <= 0: exp2 via degree-5 minimax poly on FMA pipe (no MUFU)
__device__ __forceinline__ float fast_exp_neg(float t) {
    float z = fmaxf(t * 1.4426950408889634f, -120.0f);
    float fi = floorf(z);
    float f = z - fi;
    float p =              0.00133335581f;
    p = fmaf(p, f,         0.00961812910f);
    p = fmaf(p, f,         0.0555041086f);
    p = fmaf(p, f,         0.240226462f);
    p = fmaf(p, f,         0.693147182f);
    p = fmaf(p, f,         1.0f);
    return p * __int_as_float(((int)fi + 127) << 23);
}

// smem float-index with XOR swizzle: row stride 32 floats (128B), 16B chunks
#define SWZ(r, k) (((r) * 32) + ((k) ^ (((r) & 7) * 4)))

extern __shared__ float dynsm_f[];

// ---------------------------------------------------------------------------
// Narrow GEMM core (128x128 tile, 3-stage, used by proj): unchanged from R9.
// ---------------------------------------------------------------------------
template <int PASSES>
__device__ __forceinline__ void gemm_core(
    const float* __restrict__ A, int lda,
    const float* __restrict__ Bm, int ldb,
    int nK, float acc[4][4][4])
{
    float* sm = dynsm_f;
    const int tid  = threadIdx.x;
    const int lr   = tid >> 3;
    const int lc4  = (tid & 7) * 4;
    const int lane = tid & 31, warp = tid >> 5;
    const int wr = warp >> 2, wc = warp & 3;
    const int g = lane >> 2, tg = lane & 3;
    const int fchunk = tg >> 1;
    const int foff   = (tg & 1) << 1;

    auto issue = [&](int s, int kt) {
        const int k0 = kt * 32;
        float* sa = sm + s * 8192;
        float* sb = sa + 4096;
        #pragma unroll
        for (int p = 0; p < 4; ++p) {
            const int r = p * 32 + lr;
            cp_async16(su32(&sa[SWZ(r, lc4)]), &A [(size_t)r * lda + k0 + lc4]);
            cp_async16(su32(&sb[SWZ(r, lc4)]), &Bm[(size_t)r * ldb + k0 + lc4]);
        }
        cp_commit();
    };

    issue(0, 0);
    if (nK > 1) issue(1, 1);

    for (int kt = 0; kt < nK; ++kt) {
        const int s = kt % 3;
        if (kt + 1 < nK) cp_wait1(); else cp_wait0();
        __syncthreads();
        if (kt + 2 < nK) issue((kt + 2) % 3, kt + 2);

        const float* sa = sm + s * 8192;
        const float* sb = sa + 4096;
        #pragma unroll
        for (int k8 = 0; k8 < 4; ++k8) {
            const int chunk = (k8 << 1) | fchunk;
            uint32_t afh[4][4], afl[4][4], bfh[4][2], bfl[4][2];
            #pragma unroll
            for (int am = 0; am < 4; ++am) {
                const int r0 = wr * 64 + am * 16 + g;
                const int r1 = r0 + 8;
                float2 p0 = *reinterpret_cast<const float2*>(
                    &sa[r0 * 32 + ((chunk ^ (r0 & 7)) << 2) + foff]);
                float2 p1 = *reinterpret_cast<const float2*>(
                    &sa[r1 * 32 + ((chunk ^ (r1 & 7)) << 2) + foff]);
                if (PASSES >= 2) {
                    split_m(p0.x, afh[am][0], afl[am][0]);
                    split_m(p1.x, afh[am][1], afl[am][1]);
                    split_m(p0.y, afh[am][2], afl[am][2]);
                    split_m(p1.y, afh[am][3], afl[am][3]);
                } else {
                    afh[am][0] = __float_as_uint(p0.x);
                    afh[am][1] = __float_as_uint(p1.x);
                    afh[am][2] = __float_as_uint(p0.y);
                    afh[am][3] = __float_as_uint(p1.y);
                }
            }
            #pragma unroll
            for (int bn = 0; bn < 4; ++bn) {
                const int rb = wc * 32 + bn * 8 + g;
                float2 q = *reinterpret_cast<const float2*>(
                    &sb[rb * 32 + ((chunk ^ (rb & 7)) << 2) + foff]);
                if (PASSES == 3) {
                    split_m(q.x, bfh[bn][0], bfl[bn][0]);
                    split_m(q.y, bfh[bn][1], bfl[bn][1]);
                } else {
                    bfh[bn][0] = __float_as_uint(q.x);
                    bfh[bn][1] = __float_as_uint(q.y);
                }
            }
            #pragma unroll
            for (int am = 0; am < 4; ++am)
                #pragma unroll
                for (int bn = 0; bn < 4; ++bn)
                    mma_tf32(acc[am][bn], afh[am], bfh[bn]);
            if (PASSES == 3) {
                #pragma unroll
                for (int am = 0; am < 4; ++am)
                    #pragma unroll
                    for (int bn = 0; bn < 4; ++bn)
                        mma_tf32(acc[am][bn], afh[am], bfl[bn]);
            }
            if (PASSES >= 2) {
                #pragma unroll
                for (int am = 0; am < 4; ++am)
                    #pragma unroll
                    for (int bn = 0; bn < 4; ++bn)
                        mma_tf32(acc[am][bn], afl[am], bfh[bn]);
            }
        }
    }
}

// ---------------------------------------------------------------------------
// WIDE GEMM core: D[128 x 256] += A[128 x K] @ B[256 x K]^T, 2-stage smem
// (48KB/stage: A 16KB + B 32KB), warp tile 64x64 -> 32 MMA per pass per k8.
// 1 CTA/SM (acc = 128 regs). Same per-element reduction order as narrow core.
// ---------------------------------------------------------------------------
template <int PASSES>
__device__ __forceinline__ void gemm_core_w(
    const float* __restrict__ A, int lda,
    const float* __restrict__ Bm, int ldb,
    int nK, float acc[4][8][4])
{
    float* sm = dynsm_f;
    const int tid  = threadIdx.x;
    const int lr   = tid >> 3;
    const int lc4  = (tid & 7) * 4;
    const int lane = tid & 31, warp = tid >> 5;
    const int wr = warp >> 2, wc = warp & 3;
    const int g = lane >> 2, tg = lane & 3;
    const int fchunk = tg >> 1;
    const int foff   = (tg & 1) << 1;

    auto issue = [&](int s, int kt) {
        const int k0 = kt * 32;
        float* sa = sm + s * 12288;            // stage: A[0,16KB) B[16KB,48KB)
        float* sb = sa + 4096;
        #pragma unroll
        for (int p = 0; p < 4; ++p) {
            const int r = p * 32 + lr;
            cp_async16(su32(&sa[SWZ(r, lc4)]), &A[(size_t)r * lda + k0 + lc4]);
        }
        #pragma unroll
        for (int p = 0; p < 8; ++p) {
            const int r = p * 32 + lr;
            cp_async16(su32(&sb[SWZ(r, lc4)]), &Bm[(size_t)r * ldb + k0 + lc4]);
        }
        cp_commit();
    };

    issue(0, 0);

    for (int kt = 0; kt < nK; ++kt) {
        const int s = kt & 1;
        cp_wait0();
        __syncthreads();
        if (kt + 1 < nK) issue(s ^ 1, kt + 1);

        const float* sa = sm + s * 12288;
        const float* sb = sa + 4096;
        #pragma unroll
        for (int k8 = 0; k8 < 4; ++k8) {
            const int chunk = (k8 << 1) | fchunk;
            uint32_t afh[4][4], afl[4][4], bfh[8][2], bfl[8][2];
            #pragma unroll
            for (int am = 0; am < 4; ++am) {
                const int r0 = wr * 64 + am * 16 + g;
                const int r1 = r0 + 8;
                float2 p0 = *reinterpret_cast<const float2*>(
                    &sa[r0 * 32 + ((chunk ^ (r0 & 7)) << 2) + foff]);
                float2 p1 = *reinterpret_cast<const float2*>(
                    &sa[r1 * 32 + ((chunk ^ (r1 & 7)) << 2) + foff]);
                if (PASSES >= 2) {
                    split_m(p0.x, afh[am][0], afl[am][0]);
                    split_m(p1.x, afh[am][1], afl[am][1]);
                    split_m(p0.y, afh[am][2], afl[am][2]);
                    split_m(p1.y, afh[am][3], afl[am][3]);
                } else {
                    afh[am][0] = __float_as_uint(p0.x);
                    afh[am][1] = __float_as_uint(p1.x);
                    afh[am][2] = __float_as_uint(p0.y);
                    afh[am][3] = __float_as_uint(p1.y);
                }
            }
            #pragma unroll
            for (int bn = 0; bn < 8; ++bn) {
                const int rb = wc * 64 + bn * 8 + g;
                float2 q = *reinterpret_cast<const float2*>(
                    &sb[rb * 32 + ((chunk ^ (rb & 7)) << 2) + foff]);
                if (PASSES == 3) {
                    split_m(q.x, bfh[bn][0], bfl[bn][0]);
                    split_m(q.y, bfh[bn][1], bfl[bn][1]);
                } else {
                    bfh[bn][0] = __float_as_uint(q.x);
                    bfh[bn][1] = __float_as_uint(q.y);
                }
            }
            #pragma unroll
            for (int am = 0; am < 4; ++am)
                #pragma unroll
                for (int bn = 0; bn < 8; ++bn)
                    mma_tf32(acc[am][bn], afh[am], bfh[bn]);
            if (PASSES == 3) {
                #pragma unroll
                for (int am = 0; am < 4; ++am)
                    #pragma unroll
                    for (int bn = 0; bn < 8; ++bn)
                        mma_tf32(acc[am][bn], afh[am], bfl[bn]);
            }
            if (PASSES >= 2) {
                #pragma unroll
                for (int am = 0; am < 4; ++am)
                    #pragma unroll
                    for (int bn = 0; bn < 8; ++bn)
                        mma_tf32(acc[am][bn], afl[am], bfh[bn]);
            }
        }
    }
}

// ---------------------------------------------------------------------------
// Epilogues
// ---------------------------------------------------------------------------
__device__ __forceinline__ void epi_store_perm(
    float acc[4][4][4], float* __restrict__ Out, int ld,
    const float* __restrict__ bias_col, const float* __restrict__ bias_row,
    bool round_tf)
{
    const int lane = threadIdx.x & 31, warp = threadIdx.x >> 5;
    const int wr = warp >> 2, wc = warp & 3;
    const int g = lane >> 2, tg = lane & 3;
    #pragma unroll
    for (int am = 0; am < 4; ++am) {
        const int r = wr * 64 + am * 16 + g;
        const float br0 = bias_row ? bias_row[r]     : 0.f;
        const float br1 = bias_row ? bias_row[r + 8] : 0.f;
        #pragma unroll
        for (int bn = 0; bn < 4; ++bn) {
            const int c = wc * 32 + bn * 8 + tg * 2;
            const float b0 = bias_col ? bias_col[c]     : 0.f;
            const float b1 = bias_col ? bias_col[c + 1] : 0.f;
            float e0 = acc[am][bn][0] + b0 + br0;
            float e1 = acc[am][bn][1] + b1 + br0;
            float e2 = acc[am][bn][2] + b0 + br1;
            float e3 = acc[am][bn][3] + b1 + br1;
            if (round_tf) {
                e0 = __uint_as_float(f2tf(e0));
                e1 = __uint_as_float(f2tf(e1));
                e2 = __uint_as_float(f2tf(e2));
                e3 = __uint_as_float(f2tf(e3));
            }
            const int p0 = (c & ~7) | perm8(c & 7);
            const int p1 = (c & ~7) | perm8((c & 7) + 1);
            Out[(size_t)r       * ld + p0] = e0;
            Out[(size_t)r       * ld + p1] = e1;
            Out[(size_t)(r + 8) * ld + p0] = e2;
            Out[(size_t)(r + 8) * ld + p1] = e3;
        }
    }
}

// Wide epilogue, natural columns (residual -> harness out).
__device__ __forceinline__ void epi_store_w(
    float acc[4][8][4], float* __restrict__ Out, int ld)
{
    const int lane = threadIdx.x & 31, warp = threadIdx.x >> 5;
    const int wr = warp >> 2, wc = warp & 3;
    const int g = lane >> 2, tg = lane & 3;
    #pragma unroll
    for (int am = 0; am < 4; ++am) {
        const int r = wr * 64 + am * 16 + g;
        #pragma unroll
        for (int bn = 0; bn < 8; ++bn) {
            const int c = wc * 64 + bn * 8 + tg * 2;
            float2 v0 = { acc[am][bn][0], acc[am][bn][1] };
            float2 v1 = { acc[am][bn][2], acc[am][bn][3] };
            *reinterpret_cast<float2*>(&Out[(size_t)r       * ld + c]) = v0;
            *reinterpret_cast<float2*>(&Out[(size_t)(r + 8) * ld + c]) = v1;
        }
    }
}

// Wide epilogue, permuted columns (energy -> g_E).
__device__ __forceinline__ void epi_store_perm_w(
    float acc[4][8][4], float* __restrict__ Out, int ld)
{
    const int lane = threadIdx.x & 31, warp = threadIdx.x >> 5;
    const int wr = warp >> 2, wc = warp & 3;
    const int g = lane >> 2, tg = lane & 3;
    #pragma unroll
    for (int am = 0; am < 4; ++am) {
        const int r = wr * 64 + am * 16 + g;
        #pragma unroll
        for (int bn = 0; bn < 8; ++bn) {
            const int c = wc * 64 + bn * 8 + tg * 2;
            const int p0 = (c & ~7) | perm8(c & 7);
            const int p1 = (c & ~7) | perm8((c & 7) + 1);
            Out[(size_t)r       * ld + p0] = acc[am][bn][0];
            Out[(size_t)r       * ld + p1] = acc[am][bn][1];
            Out[(size_t)(r + 8) * ld + p0] = acc[am][bn][2];
            Out[(size_t)(r + 8) * ld + p1] = acc[am][bn][3];
        }
    }
}

// ---------------------------------------------------------------------------
// Producers
// ---------------------------------------------------------------------------
__global__ __launch_bounds__(256) void permute_w_kernel(
    const float* __restrict__ Wf, const float* __restrict__ Wg,
    const float* __restrict__ Wh)
{
    const int i = blockIdx.x * 256 + threadIdx.x;
    const int NW = (HC_ + HC_ + C_) * C_;
    if (i >= NW) return;
    float v;
    if (i < HC_ * C_)           v = Wf[i];
    else if (i < 2 * HC_ * C_)  v = Wg[i - HC_ * C_];
    else                        v = Wh[i - 2 * HC_ * C_];
    const int o = i / C_, c = i % C_;
    g_Wp[(size_t)o * C_ + permpos(c)] = v;
}

__global__ __launch_bounds__(256) void transpose_x_kernel(const float* __restrict__ x)
{
    __shared__ float t[32][33];
    const int b = blockIdx.z, n0 = blockIdx.x * 32, c0 = blockIdx.y * 32;
    const int tx = threadIdx.x, ty = threadIdx.y;
    const float* X = x + (size_t)b * C_ * N_;
    float* XT = g_xt + (size_t)b * N_ * C_;
    #pragma unroll
    for (int i = 0; i < 4; ++i)
        t[ty + i * 8][tx] = X[(size_t)(c0 + ty + i * 8) * N_ + n0 + tx];
    __syncthreads();
    const int cp = c0 + permpos(tx);
    #pragma unroll
    for (int i = 0; i < 4; ++i)
        XT[(size_t)(n0 + ty + i * 8) * C_ + cp] = t[tx][ty + i * 8];
}

// ---------------------------------------------------------------------------
// Merged projection kernel (narrow core, 3xTF32).
// ---------------------------------------------------------------------------
__global__ __launch_bounds__(256, 2) void proj_kernel(
    const float* __restrict__ bf, const float* __restrict__ bg,
    const float* __restrict__ bh)
{
    const int b = blockIdx.z, n0 = blockIdx.x * 128, yt = blockIdx.y;
    float acc[4][4][4] = {};

    if (yt < 4) {
        const float* A = g_xt + ((size_t)b * N_ + n0) * C_;
        const float* W; const float* bias; float* Out; int o0; bool rnd;
        if (yt < 2) { W = g_Wp + (size_t)(yt * 128) * C_;             bias = bf + yt * 128;       Out = g_ft + (size_t)b * N_ * HC_; o0 = yt * 128;       rnd = false; }
        else        { W = g_Wp + (size_t)(HC_ + (yt - 2) * 128) * C_; bias = bg + (yt - 2) * 128; Out = g_gt + (size_t)b * N_ * HC_; o0 = (yt - 2) * 128; rnd = true;  }
        gemm_core<3>(A, C_, W, C_, C_ / 32, acc);
        epi_store_perm(acc, Out + (size_t)n0 * HC_ + o0, HC_, bias, nullptr, rnd);
    } else {
        const int c0 = (yt - 4) * 128;
        const float* A  = g_Wp + (size_t)(2 * HC_ + c0) * C_;
        const float* Bm = g_xt + ((size_t)b * N_ + n0) * C_;
        gemm_core<3>(A, C_, Bm, C_, C_ / 32, acc);
        epi_store_perm(acc, g_h + (size_t)b * C_ * N_ + (size_t)c0 * N_ + n0, N_, nullptr, bh + c0, true);
    }
}

// energy: D[j][k] = ft[j][:] . gt[k][:] -> [j][k-perm]; wide tile 128x256.
__global__ __launch_bounds__(256, 1) void energy_kernel()
{
    const int b = blockIdx.z, k0 = blockIdx.x * 256, j0 = blockIdx.y * 128;
    const float* A  = g_ft + ((size_t)b * N_ + j0) * HC_;
    const float* Bm = g_gt + ((size_t)b * N_ + k0) * HC_;

    float acc[4][8][4] = {};
    gemm_core_w<2>(A, HC_, Bm, HC_, HC_ / 32, acc);
    epi_store_perm_w(acc, g_E + (size_t)b * N_ * N_ + (size_t)j0 * N_ + k0, N_);
}

// residual: D[c][j] = h[c][:] . corr[j][:] — wide tile 128x256, 1-pass.
__global__ __launch_bounds__(256, 1) void residual_kernel(float* __restrict__ out)
{
    const int b = blockIdx.z, c0 = blockIdx.x * 128, j0 = blockIdx.y * 256;
    const float* A  = g_h + (size_t)b * C_ * N_ + (size_t)c0 * N_;
    const float* Bm = g_E + (size_t)b * N_ * N_ + (size_t)j0 * N_;

    float acc[4][8][4] = {};
    gemm_core_w<1>(A, N_, Bm, N_, N_ / 32, acc);
    epi_store_w(acc, out + (size_t)b * C_ * N_ + (size_t)c0 * N_ + j0, N_);
}

// ---------------------------------------------------------------------------
// Softmax over 8 rows per block; writes corr rounded to tf32 AND per-block
// column partial sums (colmean fused).
// ---------------------------------------------------------------------------
__global__ __launch_bounds__(256) void softmax_kernel()
{
    const int b = blockIdx.y;
    const int j0 = blockIdx.x * 8;
    const int tid = threadIdx.x;
    __shared__ float red[8];

    float colacc[16];
    #pragma unroll
    for (int i = 0; i < 16; ++i) colacc[i] = 0.f;

    for (int r = 0; r < 8; ++r) {
        float* row = g_E + ((size_t)b * N_ + j0 + r) * N_;

        float v[16];
        float m = -CUDART_INF_F;
        #pragma unroll
        for (int i = 0; i < 16; ++i) { v[i] = row[tid + i * 256]; m = fmaxf(m, v[i]); }

        #pragma unroll
        for (int o = 16; o; o >>= 1) m = fmaxf(m, __shfl_xor_sync(0xffffffffu, m, o));
        if ((tid & 31) == 0) red[tid >> 5] = m;
        __syncthreads();
        {
            float t = (tid < 8) ? red[tid] : -CUDART_INF_F;
            #pragma unroll
            for (int o = 4; o; o >>= 1) t = fmaxf(t, __shfl_xor_sync(0xffffffffu, t, o));
            if (tid == 0) red[0] = t;
        }
        __syncthreads();
        m = red[0];
        __syncthreads();

        float s = 0.f;
        #pragma unroll
        for (int i = 0; i < 16; ++i) { v[i] = fast_exp_neg(v[i] - m); s += v[i]; }
        #pragma unroll
        for (int o = 16; o; o >>= 1) s += __shfl_xor_sync(0xffffffffu, s, o);
        if ((tid & 31) == 0) red[tid >> 5] = s;
        __syncthreads();
        {
            float t = (tid < 8) ? red[tid] : 0.f;
            #pragma unroll
            for (int o = 4; o; o >>= 1) t += __shfl_xor_sync(0xffffffffu, t, o);
            if (tid == 0) red[0] = t;
        }
        __syncthreads();
        const float inv = 1.0f / red[0];
        __syncthreads();

        #pragma unroll
        for (int i = 0; i < 16; ++i) {
            const float c = __uint_as_float(f2tf(v[i] * inv));
            row[tid + i * 256] = c;
            colacc[i] += c;
        }
    }

    float* part = g_part + ((size_t)b * 512 + blockIdx.x) * N_;
    #pragma unroll
    for (int i = 0; i < 16; ++i) part[tid + i * 256] = colacc[i];
}

// Column mean final: sum 512 partials per column; un-permute output index.
__global__ __launch_bounds__(256) void colmean_final_kernel(float* __restrict__ out)
{
    const int b = blockIdx.y;
    const int col = blockIdx.x * 256 + threadIdx.x;  // permuted position
    const float* part = g_part + (size_t)b * 512 * N_;
    float s = 0.f;
    #pragma unroll 8
    for (int p = 0; p < 512; ++p) s += part[(size_t)p * N_ + col];
    const int m = (col & ~7) | ((col & 7) >> 1) | ((col & 1) << 2);  // iperm8
    out[(size_t)B_ * C_ * N_ + (size_t)b * N_ + m] = s * (1.0f / N_);
}

// ---------------------------------------------------------------------------
extern "C" void kernel_launch(void* const* d_in, const int* in_sizes, int n_in,
                              void* d_out, int out_size)
{
    const float* x  = (const float*)d_in[0];
    const float* Wf = (const float*)d_in[1];
    const float* bf = (const float*)d_in[2];
    const float* Wg = (const float*)d_in[3];
    const float* bg = (const float*)d_in[4];
    const float* Wh = (const float*)d_in[5];
    const float* bh = (const float*)d_in[6];
    float* out = (float*)d_out;

    const int SMEM = 98304;  // narrow: 3x32KB; wide: 2x48KB
    cudaFuncSetAttribute(proj_kernel,     cudaFuncAttributeMaxDynamicSharedMemorySize, SMEM);
    cudaFuncSetAttribute(energy_kernel,   cudaFuncAttributeMaxDynamicSharedMemorySize, SMEM);
    cudaFuncSetAttribute(residual_kernel, cudaFuncAttributeMaxDynamicSharedMemorySize, SMEM);

    const int NW = (HC_ + HC_ + C_) * C_;
    permute_w_kernel<<<(NW + 255) / 256, 256>>>(Wf, Wg, Wh);
    transpose_x_kernel<<<dim3(N_ / 32, C_ / 32, B_), dim3(32, 8)>>>(x);
    proj_kernel<<<dim3(32, 8, B_), 256, SMEM>>>(bf, bg, bh);
    energy_kernel<<<dim3(16, 32, B_), 256, SMEM>>>();
    softmax_kernel<<<dim3(512, B_), 256>>>();
    colmean_final_kernel<<<dim3(16, B_), 256>>>(out);
    residual_kernel<<<dim3(4, 16, B_), 256, SMEM>>>(out);
}

// round 14
// speedup vs baseline: 2.1597x; 1.0299x over previous
#include <cuda_runtime.h>
#include <math_constants.h>
#include <cstdint>

#define B_  4
#define C_  512
#define HC_ 256
#define N_  4096

// ---------------------------------------------------------------------------
// K-group permutation: within each 8-wide K group, position p holds
// k = (0,4,1,5,2,6,3,7)[p] so that fragment pairs (k, k+4) are adjacent.
// ---------------------------------------------------------------------------
__host__ __device__ __forceinline__ int perm8(int q)  { return ((q & 3) << 1) | (q >> 2); }
__device__ __forceinline__ int permpos(int c) { return (c & ~7) | perm8(c & 7); }

// ---------------------------------------------------------------------------
// Device scratch (all K-contraction dims stored permuted)
// ---------------------------------------------------------------------------
__device__ float g_xt[(size_t)B_ * N_ * C_];    // x^T: [b][n][c-perm]
__device__ float g_Wp[(size_t)(HC_ + HC_ + C_) * C_]; // Wf|Wg|Wh, [o][c-perm]
__device__ float g_ft[(size_t)B_ * N_ * HC_];   // f^T: [b][n][hc-perm]  (fp32)
__device__ float g_gt[(size_t)B_ * N_ * HC_];   // g^T: [b][n][hc-perm]  (tf32-rounded)
__device__ float g_h [(size_t)B_ * C_ * N_];    // h:   [b][c][n-perm]   (tf32-rounded)
__device__ float g_E [(size_t)B_ * N_ * N_];    // energy/corr [b][j][k-perm]
__device__ float g_part[(size_t)B_ * 512 * N_]; // colmean partials (8 rows each)

// ---------------------------------------------------------------------------
// Helpers (baseline PTX only — ptxas targets sm_103, no 'a'-gated instrs)
// ---------------------------------------------------------------------------
__device__ __forceinline__ uint32_t su32(const void* p) {
    uint32_t a;
    asm("{ .reg .u64 t; cvta.to.shared.u64 t, %1; cvt.u32.u64 %0, t; }" : "=r"(a) : "l"(p));
    return a;
}
__device__ __forceinline__ void cp_async16(uint32_t dst, const void* src) {
    asm volatile("cp.async.cg.shared.global [%0], [%1], 16;" :: "r"(dst), "l"(src) : "memory");
}
__device__ __forceinline__ void cp_commit() {
    asm volatile("cp.async.commit_group;" ::: "memory");
}
__device__ __forceinline__ void cp_wait0() {
    asm volatile("cp.async.wait_group 0;" ::: "memory");
}
__device__ __forceinline__ void cp_wait1() {
    asm volatile("cp.async.wait_group 1;" ::: "memory");
}
__device__ __forceinline__ uint32_t f2tf(float f) {
    uint32_t r;
    asm("cvt.rna.tf32.f32 %0, %1;" : "=r"(r) : "f"(f));
    return r;
}
// Truncation-based split: hi = top tf32 bits (LOP3), lo = v - hi (exact).
__device__ __forceinline__ void split_m(float v, uint32_t& hi, uint32_t& lo) {
    hi = __float_as_uint(v) & 0xFFFFE000u;
    lo = __float_as_uint(v - __uint_as_float(hi));
}
__device__ __forceinline__ void mma_tf32(float* d, const uint32_t* a, const uint32_t* b) {
    asm volatile(
        "mma.sync.aligned.m16n8k8.row.col.f32.tf32.tf32.f32 "
        "{%0,%1,%2,%3}, {%4,%5,%6,%7}, {%8,%9}, {%0,%1,%2,%3};"
        : "+f"(d[0]), "+f"(d[1]), "+f"(d[2]), "+f"(d[3])
        : "r"(a[0]), "r"(a[1]), "r"(a[2]), "r"(a[3]), "r"(b[0]), "r"(b[1]));
}

// fast exp(t) for t <= 0: exp2 via degree-5 minimax poly on FMA pipe (no MUFU)
__device__ __forceinline__ float fast_exp_neg(float t) {
    float z = fmaxf(t * 1.4426950408889634f, -120.0f);
    float fi = floorf(z);
    float f = z - fi;
    float p =              0.00133335581f;
    p = fmaf(p, f,         0.00961812910f);
    p = fmaf(p, f,         0.0555041086f);
    p = fmaf(p, f,         0.240226462f);
    p = fmaf(p, f,         0.693147182f);
    p = fmaf(p, f,         1.0f);
    return p * __int_as_float(((int)fi + 127) << 23);
}

// smem float-index with XOR swizzle: row stride 32 floats (128B), 16B chunks
#define SWZ(r, k) (((r) * 32) + ((k) ^ (((r) & 7) * 4)))

extern __shared__ float dynsm_f[];

// ---------------------------------------------------------------------------
// Narrow GEMM core (128x128 tile, 3-stage, 2 CTAs/SM): proj + energy.
// ---------------------------------------------------------------------------
template <int PASSES>
__device__ __forceinline__ void gemm_core(
    const float* __restrict__ A, int lda,
    const float* __restrict__ Bm, int ldb,
    int nK, float acc[4][4][4])
{
    float* sm = dynsm_f;
    const int tid  = threadIdx.x;
    const int lr   = tid >> 3;
    const int lc4  = (tid & 7) * 4;
    const int lane = tid & 31, warp = tid >> 5;
    const int wr = warp >> 2, wc = warp & 3;
    const int g = lane >> 2, tg = lane & 3;
    const int fchunk = tg >> 1;
    const int foff   = (tg & 1) << 1;

    auto issue = [&](int s, int kt) {
        const int k0 = kt * 32;
        float* sa = sm + s * 8192;
        float* sb = sa + 4096;
        #pragma unroll
        for (int p = 0; p < 4; ++p) {
            const int r = p * 32 + lr;
            cp_async16(su32(&sa[SWZ(r, lc4)]), &A [(size_t)r * lda + k0 + lc4]);
            cp_async16(su32(&sb[SWZ(r, lc4)]), &Bm[(size_t)r * ldb + k0 + lc4]);
        }
        cp_commit();
    };

    issue(0, 0);
    if (nK > 1) issue(1, 1);

    for (int kt = 0; kt < nK; ++kt) {
        const int s = kt % 3;
        if (kt + 1 < nK) cp_wait1(); else cp_wait0();
        __syncthreads();
        if (kt + 2 < nK) issue((kt + 2) % 3, kt + 2);

        const float* sa = sm + s * 8192;
        const float* sb = sa + 4096;
        #pragma unroll
        for (int k8 = 0; k8 < 4; ++k8) {
            const int chunk = (k8 << 1) | fchunk;
            uint32_t afh[4][4], afl[4][4], bfh[4][2], bfl[4][2];
            #pragma unroll
            for (int am = 0; am < 4; ++am) {
                const int r0 = wr * 64 + am * 16 + g;
                const int r1 = r0 + 8;
                float2 p0 = *reinterpret_cast<const float2*>(
                    &sa[r0 * 32 + ((chunk ^ (r0 & 7)) << 2) + foff]);
                float2 p1 = *reinterpret_cast<const float2*>(
                    &sa[r1 * 32 + ((chunk ^ (r1 & 7)) << 2) + foff]);
                if (PASSES >= 2) {
                    split_m(p0.x, afh[am][0], afl[am][0]);
                    split_m(p1.x, afh[am][1], afl[am][1]);
                    split_m(p0.y, afh[am][2], afl[am][2]);
                    split_m(p1.y, afh[am][3], afl[am][3]);
                } else {
                    afh[am][0] = __float_as_uint(p0.x);
                    afh[am][1] = __float_as_uint(p1.x);
                    afh[am][2] = __float_as_uint(p0.y);
                    afh[am][3] = __float_as_uint(p1.y);
                }
            }
            #pragma unroll
            for (int bn = 0; bn < 4; ++bn) {
                const int rb = wc * 32 + bn * 8 + g;
                float2 q = *reinterpret_cast<const float2*>(
                    &sb[rb * 32 + ((chunk ^ (rb & 7)) << 2) + foff]);
                if (PASSES == 3) {
                    split_m(q.x, bfh[bn][0], bfl[bn][0]);
                    split_m(q.y, bfh[bn][1], bfl[bn][1]);
                } else {
                    bfh[bn][0] = __float_as_uint(q.x);
                    bfh[bn][1] = __float_as_uint(q.y);
                }
            }
            #pragma unroll
            for (int am = 0; am < 4; ++am)
                #pragma unroll
                for (int bn = 0; bn < 4; ++bn)
                    mma_tf32(acc[am][bn], afh[am], bfh[bn]);
            if (PASSES == 3) {
                #pragma unroll
                for (int am = 0; am < 4; ++am)
                    #pragma unroll
                    for (int bn = 0; bn < 4; ++bn)
                        mma_tf32(acc[am][bn], afh[am], bfl[bn]);
            }
            if (PASSES >= 2) {
                #pragma unroll
                for (int am = 0; am < 4; ++am)
                    #pragma unroll
                    for (int bn = 0; bn < 4; ++bn)
                        mma_tf32(acc[am][bn], afl[am], bfh[bn]);
            }
        }
    }
}

// ---------------------------------------------------------------------------
// WIDE GEMM core: D[128 x 256], 2-stage, 1 CTA/SM. Residual only (1-pass:
// thin issue stream tolerates the lower occupancy; halves h re-reads).
// ---------------------------------------------------------------------------
template <int PASSES>
__device__ __forceinline__ void gemm_core_w(
    const float* __restrict__ A, int lda,
    const float* __restrict__ Bm, int ldb,
    int nK, float acc[4][8][4])
{
    float* sm = dynsm_f;
    const int tid  = threadIdx.x;
    const int lr   = tid >> 3;
    const int lc4  = (tid & 7) * 4;
    const int lane = tid & 31, warp = tid >> 5;
    const int wr = warp >> 2, wc = warp & 3;
    const int g = lane >> 2, tg = lane & 3;
    const int fchunk = tg >> 1;
    const int foff   = (tg & 1) << 1;

    auto issue = [&](int s, int kt) {
        const int k0 = kt * 32;
        float* sa = sm + s * 12288;            // stage: A[0,16KB) B[16KB,48KB)
        float* sb = sa + 4096;
        #pragma unroll
        for (int p = 0; p < 4; ++p) {
            const int r = p * 32 + lr;
            cp_async16(su32(&sa[SWZ(r, lc4)]), &A[(size_t)r * lda + k0 + lc4]);
        }
        #pragma unroll
        for (int p = 0; p < 8; ++p) {
            const int r = p * 32 + lr;
            cp_async16(su32(&sb[SWZ(r, lc4)]), &Bm[(size_t)r * ldb + k0 + lc4]);
        }
        cp_commit();
    };

    issue(0, 0);

    for (int kt = 0; kt < nK; ++kt) {
        const int s = kt & 1;
        cp_wait0();
        __syncthreads();
        if (kt + 1 < nK) issue(s ^ 1, kt + 1);

        const float* sa = sm + s * 12288;
        const float* sb = sa + 4096;
        #pragma unroll
        for (int k8 = 0; k8 < 4; ++k8) {
            const int chunk = (k8 << 1) | fchunk;
            uint32_t afh[4][4], afl[4][4], bfh[8][2], bfl[8][2];
            #pragma unroll
            for (int am = 0; am < 4; ++am) {
                const int r0 = wr * 64 + am * 16 + g;
                const int r1 = r0 + 8;
                float2 p0 = *reinterpret_cast<const float2*>(
                    &sa[r0 * 32 + ((chunk ^ (r0 & 7)) << 2) + foff]);
                float2 p1 = *reinterpret_cast<const float2*>(
                    &sa[r1 * 32 + ((chunk ^ (r1 & 7)) << 2) + foff]);
                if (PASSES >= 2) {
                    split_m(p0.x, afh[am][0], afl[am][0]);
                    split_m(p1.x, afh[am][1], afl[am][1]);
                    split_m(p0.y, afh[am][2], afl[am][2]);
                    split_m(p1.y, afh[am][3], afl[am][3]);
                } else {
                    afh[am][0] = __float_as_uint(p0.x);
                    afh[am][1] = __float_as_uint(p1.x);
                    afh[am][2] = __float_as_uint(p0.y);
                    afh[am][3] = __float_as_uint(p1.y);
                }
            }
            #pragma unroll
            for (int bn = 0; bn < 8; ++bn) {
                const int rb = wc * 64 + bn * 8 + g;
                float2 q = *reinterpret_cast<const float2*>(
                    &sb[rb * 32 + ((chunk ^ (rb & 7)) << 2) + foff]);
                if (PASSES == 3) {
                    split_m(q.x, bfh[bn][0], bfl[bn][0]);
                    split_m(q.y, bfh[bn][1], bfl[bn][1]);
                } else {
                    bfh[bn][0] = __float_as_uint(q.x);
                    bfh[bn][1] = __float_as_uint(q.y);
                }
            }
            #pragma unroll
            for (int am = 0; am < 4; ++am)
                #pragma unroll
                for (int bn = 0; bn < 8; ++bn)
                    mma_tf32(acc[am][bn], afh[am], bfh[bn]);
            if (PASSES == 3) {
                #pragma unroll
                for (int am = 0; am < 4; ++am)
                    #pragma unroll
                    for (int bn = 0; bn < 8; ++bn)
                        mma_tf32(acc[am][bn], afh[am], bfl[bn]);
            }
            if (PASSES >= 2) {
                #pragma unroll
                for (int am = 0; am < 4; ++am)
                    #pragma unroll
                    for (int bn = 0; bn < 8; ++bn)
                        mma_tf32(acc[am][bn], afl[am], bfh[bn]);
            }
        }
    }
}

// ---------------------------------------------------------------------------
// Epilogues
// ---------------------------------------------------------------------------
__device__ __forceinline__ void epi_store_perm(
    float acc[4][4][4], float* __restrict__ Out, int ld,
    const float* __restrict__ bias_col, const float* __restrict__ bias_row,
    bool round_tf)
{
    const int lane = threadIdx.x & 31, warp = threadIdx.x >> 5;
    const int wr = warp >> 2, wc = warp & 3;
    const int g = lane >> 2, tg = lane & 3;
    #pragma unroll
    for (int am = 0; am < 4; ++am) {
        const int r = wr * 64 + am * 16 + g;
        const float br0 = bias_row ? bias_row[r]     : 0.f;
        const float br1 = bias_row ? bias_row[r + 8] : 0.f;
        #pragma unroll
        for (int bn = 0; bn < 4; ++bn) {
            const int c = wc * 32 + bn * 8 + tg * 2;
            const float b0 = bias_col ? bias_col[c]     : 0.f;
            const float b1 = bias_col ? bias_col[c + 1] : 0.f;
            float e0 = acc[am][bn][0] + b0 + br0;
            float e1 = acc[am][bn][1] + b1 + br0;
            float e2 = acc[am][bn][2] + b0 + br1;
            float e3 = acc[am][bn][3] + b1 + br1;
            if (round_tf) {
                e0 = __uint_as_float(f2tf(e0));
                e1 = __uint_as_float(f2tf(e1));
                e2 = __uint_as_float(f2tf(e2));
                e3 = __uint_as_float(f2tf(e3));
            }
            const int p0 = (c & ~7) | perm8(c & 7);
            const int p1 = (c & ~7) | perm8((c & 7) + 1);
            Out[(size_t)r       * ld + p0] = e0;
            Out[(size_t)r       * ld + p1] = e1;
            Out[(size_t)(r + 8) * ld + p0] = e2;
            Out[(size_t)(r + 8) * ld + p1] = e3;
        }
    }
}

// Wide epilogue, natural columns (residual -> harness out).
__device__ __forceinline__ void epi_store_w(
    float acc[4][8][4], float* __restrict__ Out, int ld)
{
    const int lane = threadIdx.x & 31, warp = threadIdx.x >> 5;
    const int wr = warp >> 2, wc = warp & 3;
    const int g = lane >> 2, tg = lane & 3;
    #pragma unroll
    for (int am = 0; am < 4; ++am) {
        const int r = wr * 64 + am * 16 + g;
        #pragma unroll
        for (int bn = 0; bn < 8; ++bn) {
            const int c = wc * 64 + bn * 8 + tg * 2;
            float2 v0 = { acc[am][bn][0], acc[am][bn][1] };
            float2 v1 = { acc[am][bn][2], acc[am][bn][3] };
            *reinterpret_cast<float2*>(&Out[(size_t)r       * ld + c]) = v0;
            *reinterpret_cast<float2*>(&Out[(size_t)(r + 8) * ld + c]) = v1;
        }
    }
}

// ---------------------------------------------------------------------------
// Producers
// ---------------------------------------------------------------------------
__global__ __launch_bounds__(256) void permute_w_kernel(
    const float* __restrict__ Wf, const float* __restrict__ Wg,
    const float* __restrict__ Wh)
{
    const int i = blockIdx.x * 256 + threadIdx.x;
    const int NW = (HC_ + HC_ + C_) * C_;
    if (i >= NW) return;
    float v;
    if (i < HC_ * C_)           v = Wf[i];
    else if (i < 2 * HC_ * C_)  v = Wg[i - HC_ * C_];
    else                        v = Wh[i - 2 * HC_ * C_];
    const int o = i / C_, c = i % C_;
    g_Wp[(size_t)o * C_ + permpos(c)] = v;
}

__global__ __launch_bounds__(256) void transpose_x_kernel(const float* __restrict__ x)
{
    __shared__ float t[32][33];
    const int b = blockIdx.z, n0 = blockIdx.x * 32, c0 = blockIdx.y * 32;
    const int tx = threadIdx.x, ty = threadIdx.y;
    const float* X = x + (size_t)b * C_ * N_;
    float* XT = g_xt + (size_t)b * N_ * C_;
    #pragma unroll
    for (int i = 0; i < 4; ++i)
        t[ty + i * 8][tx] = X[(size_t)(c0 + ty + i * 8) * N_ + n0 + tx];
    __syncthreads();
    const int cp = c0 + permpos(tx);
    #pragma unroll
    for (int i = 0; i < 4; ++i)
        XT[(size_t)(n0 + ty + i * 8) * C_ + cp] = t[tx][ty + i * 8];
}

// ---------------------------------------------------------------------------
// Merged projection kernel (narrow core, 3xTF32).
// ---------------------------------------------------------------------------
__global__ __launch_bounds__(256, 2) void proj_kernel(
    const float* __restrict__ bf, const float* __restrict__ bg,
    const float* __restrict__ bh)
{
    const int b = blockIdx.z, n0 = blockIdx.x * 128, yt = blockIdx.y;
    float acc[4][4][4] = {};

    if (yt < 4) {
        const float* A = g_xt + ((size_t)b * N_ + n0) * C_;
        const float* W; const float* bias; float* Out; int o0; bool rnd;
        if (yt < 2) { W = g_Wp + (size_t)(yt * 128) * C_;             bias = bf + yt * 128;       Out = g_ft + (size_t)b * N_ * HC_; o0 = yt * 128;       rnd = false; }
        else        { W = g_Wp + (size_t)(HC_ + (yt - 2) * 128) * C_; bias = bg + (yt - 2) * 128; Out = g_gt + (size_t)b * N_ * HC_; o0 = (yt - 2) * 128; rnd = true;  }
        gemm_core<3>(A, C_, W, C_, C_ / 32, acc);
        epi_store_perm(acc, Out + (size_t)n0 * HC_ + o0, HC_, bias, nullptr, rnd);
    } else {
        const int c0 = (yt - 4) * 128;
        const float* A  = g_Wp + (size_t)(2 * HC_ + c0) * C_;
        const float* Bm = g_xt + ((size_t)b * N_ + n0) * C_;
        gemm_core<3>(A, C_, Bm, C_, C_ / 32, acc);
        epi_store_perm(acc, g_h + (size_t)b * C_ * N_ + (size_t)c0 * N_ + n0, N_, nullptr, bh + c0, true);
    }
}

// energy: D[j][k] = ft[j][:] . gt[k][:] -> [j][k-perm]; narrow core, 2-pass.
__global__ __launch_bounds__(256, 2) void energy_kernel()
{
    const int b = blockIdx.z, k0 = blockIdx.x * 128, j0 = blockIdx.y * 128;
    const float* A  = g_ft + ((size_t)b * N_ + j0) * HC_;
    const float* Bm = g_gt + ((size_t)b * N_ + k0) * HC_;

    float acc[4][4][4] = {};
    gemm_core<2>(A, HC_, Bm, HC_, HC_ / 32, acc);
    epi_store_perm(acc, g_E + (size_t)b * N_ * N_ + (size_t)j0 * N_ + k0, N_, nullptr, nullptr, false);
}

// residual: D[c][j] = h[c][:] . corr[j][:] — wide tile 128x256, 1-pass.
__global__ __launch_bounds__(256, 1) void residual_kernel(float* __restrict__ out)
{
    const int b = blockIdx.z, c0 = blockIdx.x * 128, j0 = blockIdx.y * 256;
    const float* A  = g_h + (size_t)b * C_ * N_ + (size_t)c0 * N_;
    const float* Bm = g_E + (size_t)b * N_ * N_ + (size_t)j0 * N_;

    float acc[4][8][4] = {};
    gemm_core_w<1>(A, N_, Bm, N_, N_ / 32, acc);
    epi_store_w(acc, out + (size_t)b * C_ * N_ + (size_t)c0 * N_ + j0, N_);
}

// ---------------------------------------------------------------------------
// Softmax over 8 rows per block; writes corr rounded to tf32 AND per-block
// column partial sums (colmean fused).
// ---------------------------------------------------------------------------
__global__ __launch_bounds__(256) void softmax_kernel()
{
    const int b = blockIdx.y;
    const int j0 = blockIdx.x * 8;
    const int tid = threadIdx.x;
    __shared__ float red[8];

    float colacc[16];
    #pragma unroll
    for (int i = 0; i < 16; ++i) colacc[i] = 0.f;

    for (int r = 0; r < 8; ++r) {
        float* row = g_E + ((size_t)b * N_ + j0 + r) * N_;

        float v[16];
        float m = -CUDART_INF_F;
        #pragma unroll
        for (int i = 0; i < 16; ++i) { v[i] = row[tid + i * 256]; m = fmaxf(m, v[i]); }

        #pragma unroll
        for (int o = 16; o; o >>= 1) m = fmaxf(m, __shfl_xor_sync(0xffffffffu, m, o));
        if ((tid & 31) == 0) red[tid >> 5] = m;
        __syncthreads();
        {
            float t = (tid < 8) ? red[tid] : -CUDART_INF_F;
            #pragma unroll
            for (int o = 4; o; o >>= 1) t = fmaxf(t, __shfl_xor_sync(0xffffffffu, t, o));
            if (tid == 0) red[0] = t;
        }
        __syncthreads();
        m = red[0];
        __syncthreads();

        float s = 0.f;
        #pragma unroll
        for (int i = 0; i < 16; ++i) { v[i] = fast_exp_neg(v[i] - m); s += v[i]; }
        #pragma unroll
        for (int o = 16; o; o >>= 1) s += __shfl_xor_sync(0xffffffffu, s, o);
        if ((tid & 31) == 0) red[tid >> 5] = s;
        __syncthreads();
        {
            float t = (tid < 8) ? red[tid] : 0.f;
            #pragma unroll
            for (int o = 4; o; o >>= 1) t += __shfl_xor_sync(0xffffffffu, t, o);
            if (tid == 0) red[0] = t;
        }
        __syncthreads();
        const float inv = 1.0f / red[0];
        __syncthreads();

        #pragma unroll
        for (int i = 0; i < 16; ++i) {
            const float c = __uint_as_float(f2tf(v[i] * inv));
            row[tid + i * 256] = c;
            colacc[i] += c;
        }
    }

    float* part = g_part + ((size_t)b * 512 + blockIdx.x) * N_;
    #pragma unroll
    for (int i = 0; i < 16; ++i) part[tid + i * 256] = colacc[i];
}

// Column mean final: sum 512 partials per column; un-permute output index.
__global__ __launch_bounds__(256) void colmean_final_kernel(float* __restrict__ out)
{
    const int b = blockIdx.y;
    const int col = blockIdx.x * 256 + threadIdx.x;  // permuted position
    const float* part = g_part + (size_t)b * 512 * N_;
    float s = 0.f;
    #pragma unroll 8
    for (int p = 0; p < 512; ++p) s += part[(size_t)p * N_ + col];
    const int m = (col & ~7) | ((col & 7) >> 1) | ((col & 1) << 2);  // iperm8
    out[(size_t)B_ * C_ * N_ + (size_t)b * N_ + m] = s * (1.0f / N_);
}

// ---------------------------------------------------------------------------
extern "C" void kernel_launch(void* const* d_in, const int* in_sizes, int n_in,
                              void* d_out, int out_size)
{
    const float* x  = (const float*)d_in[0];
    const float* Wf = (const float*)d_in[1];
    const float* bf = (const float*)d_in[2];
    const float* Wg = (const float*)d_in[3];
    const float* bg = (const float*)d_in[4];
    const float* Wh = (const float*)d_in[5];
    const float* bh = (const float*)d_in[6];
    float* out = (float*)d_out;

    const int SMEM = 98304;  // narrow: 3x32KB; wide: 2x48KB
    cudaFuncSetAttribute(proj_kernel,     cudaFuncAttributeMaxDynamicSharedMemorySize, SMEM);
    cudaFuncSetAttribute(energy_kernel,   cudaFuncAttributeMaxDynamicSharedMemorySize, SMEM);
    cudaFuncSetAttribute(residual_kernel, cudaFuncAttributeMaxDynamicSharedMemorySize, SMEM);

    const int NW = (HC_ + HC_ + C_) * C_;
    permute_w_kernel<<<(NW + 255) / 256, 256>>>(Wf, Wg, Wh);
    transpose_x_kernel<<<dim3(N_ / 32, C_ / 32, B_), dim3(32, 8)>>>(x);
    proj_kernel<<<dim3(32, 8, B_), 256, SMEM>>>(bf, bg, bh);
    energy_kernel<<<dim3(32, 32, B_), 256, SMEM>>>();
    softmax_kernel<<<dim3(512, B_), 256>>>();
    colmean_final_kernel<<<dim3(16, B_), 256>>>(out);
    residual_kernel<<<dim3(4, 16, B_), 256, SMEM>>>(out);
}